// round 3
// baseline (speedup 1.0000x reference)
#include <cuda_runtime.h>
#include <cuda_bf16.h>
#include <cstdint>
#include <math.h>

#define SEQ 2048
#define HID 2048
#define HD  128
#define NH  16
#define NKV 4
#define EPSV 1e-6f
#define K2  (3 * HID)          // 6144 = [hi | lo | hi] concat along K
#define BK  32
#define NC  (K2 / BK)          // 192 k-chunks
#define APAD 40                // smem row stride in bf16 (80B, conflict-free for ldmatrix)

// ---------------- scratch (static device globals; no allocation) -------------
__device__ float g_Q[SEQ * HID];
__device__ float g_K[SEQ * NKV * HD];
__device__ float g_V[SEQ * NKV * HD];
__device__ float g_AO[SEQ * HID];
__device__ float g_Y[SEQ * HID];

__device__ __nv_bfloat16 g_A2[SEQ * K2];          // activations split  [hi|lo|hi]
__device__ __nv_bfloat16 g_AO2[SEQ * K2];         // attn-out split
__device__ __nv_bfloat16 g_Wq2[HID * K2];         // W^T split          [hi|hi|lo]
__device__ __nv_bfloat16 g_Wk2[(NKV*HD) * K2];
__device__ __nv_bfloat16 g_Wv2[(NKV*HD) * K2];
__device__ __nv_bfloat16 g_Wo2[HID * K2];

// ======================= warp-MMA helpers (sm_80+ path) ======================
__device__ __forceinline__ uint32_t smem_u32(const void* p) {
    uint32_t a;
    asm("{ .reg .u64 t; cvta.to.shared.u64 t, %1; cvt.u32.u64 %0, t; }" : "=r"(a) : "l"(p));
    return a;
}
__device__ __forceinline__ void ldsm4(uint32_t* r, uint32_t addr) {
    asm volatile("ldmatrix.sync.aligned.m8n8.x4.shared.b16 {%0,%1,%2,%3}, [%4];"
        : "=r"(r[0]), "=r"(r[1]), "=r"(r[2]), "=r"(r[3]) : "r"(addr));
}
__device__ __forceinline__ void mma16816(float* c, const uint32_t* a, const uint32_t* b) {
    asm volatile(
        "mma.sync.aligned.m16n8k16.row.col.f32.bf16.bf16.f32 "
        "{%0,%1,%2,%3}, {%4,%5,%6,%7}, {%8,%9}, {%0,%1,%2,%3};"
        : "+f"(c[0]), "+f"(c[1]), "+f"(c[2]), "+f"(c[3])
        : "r"(a[0]), "r"(a[1]), "r"(a[2]), "r"(a[3]), "r"(b[0]), "r"(b[1]));
}

// ===== bf16 warp-MMA GEMM: C[M,N] f32 = A[M,K2] @ B[N,K2]^T (both K-major) ===
// 128x128 block, BK=32 double-buffered, 256 threads, warp tile 64x32.
__global__ __launch_bounds__(256) void gemm_mma(const __nv_bfloat16* __restrict__ A,
                                                const __nv_bfloat16* __restrict__ B,
                                                float* __restrict__ C, int N)
{
    __shared__ __nv_bfloat16 As[2][128 * APAD];
    __shared__ __nv_bfloat16 Bs[2][128 * APAD];

    const int tid  = threadIdx.x;
    const int wid  = tid >> 5, lane = tid & 31;
    const int wm   = wid & 1;          // 2 warps over M (64 rows each)
    const int wn   = wid >> 1;         // 4 warps over N (32 cols each)
    const int bm   = blockIdx.y * 128, bn = blockIdx.x * 128;

    // global staging addresses: 2 uint4 per thread per matrix per chunk
    const int r0 = tid >> 2, u0 = tid & 3;                 // ids 0..255
    const int r1 = (256 + tid) >> 2, u1 = tid & 3;         // ids 256..511
    const __nv_bfloat16* gA0 = A + (size_t)(bm + r0) * K2 + u0 * 8;
    const __nv_bfloat16* gA1 = A + (size_t)(bm + r1) * K2 + u1 * 8;
    const __nv_bfloat16* gB0 = B + (size_t)(bn + r0) * K2 + u0 * 8;
    const __nv_bfloat16* gB1 = B + (size_t)(bn + r1) * K2 + u1 * 8;
    const int so0 = r0 * APAD + u0 * 8;                    // smem elem offsets
    const int so1 = r1 * APAD + u1 * 8;

    const uint32_t aS = smem_u32(&As[0][0]);
    const uint32_t bS = smem_u32(&Bs[0][0]);
    const uint32_t bufStride = 128 * APAD * 2;             // bytes per buffer

    // ldmatrix per-thread byte offsets (within a buffer)
    const uint32_t aRow = (uint32_t)((wm * 64 + (lane & 15)) * APAD + ((lane >> 4) << 3)) * 2;
    const uint32_t bRow = (uint32_t)((wn * 32 + (lane & 7) + (((lane >> 4) & 1) << 3)) * APAD
                                     + (((lane >> 3) & 1) << 3)) * 2;

    float acc[4][4][4];
#pragma unroll
    for (int i = 0; i < 4; i++)
#pragma unroll
        for (int j = 0; j < 4; j++)
#pragma unroll
            for (int k = 0; k < 4; k++) acc[i][j][k] = 0.0f;

    uint4 sa0, sa1, sb0, sb1;
    // preload chunk 0
    sa0 = *(const uint4*)gA0; sa1 = *(const uint4*)gA1;
    sb0 = *(const uint4*)gB0; sb1 = *(const uint4*)gB1;
    *(uint4*)&As[0][so0] = sa0; *(uint4*)&As[0][so1] = sa1;
    *(uint4*)&Bs[0][so0] = sb0; *(uint4*)&Bs[0][so1] = sb1;
    __syncthreads();

    for (int c = 0; c < NC; c++) {
        const int b = c & 1;
        const bool more = (c + 1 < NC);
        if (more) {
            const int k0 = (c + 1) * BK;
            sa0 = *(const uint4*)(gA0 + k0); sa1 = *(const uint4*)(gA1 + k0);
            sb0 = *(const uint4*)(gB0 + k0); sb1 = *(const uint4*)(gB1 + k0);
        }
        const uint32_t aBase = aS + b * bufStride;
        const uint32_t bBase = bS + b * bufStride;
#pragma unroll
        for (int ks = 0; ks < 2; ks++) {
            uint32_t af[4][4], bf[2][4];
#pragma unroll
            for (int mi = 0; mi < 4; mi++)
                ldsm4(af[mi], aBase + aRow + mi * (16 * APAD * 2) + ks * 32);
#pragma unroll
            for (int nj = 0; nj < 2; nj++)
                ldsm4(bf[nj], bBase + bRow + nj * (16 * APAD * 2) + ks * 32);
#pragma unroll
            for (int mi = 0; mi < 4; mi++) {
#pragma unroll
                for (int ni = 0; ni < 4; ni++)
                    mma16816(acc[mi][ni], af[mi], &bf[ni >> 1][(ni & 1) * 2]);
            }
        }
        if (more) {
            const int nb = 1 - b;
            *(uint4*)&As[nb][so0] = sa0; *(uint4*)&As[nb][so1] = sa1;
            *(uint4*)&Bs[nb][so0] = sb0; *(uint4*)&Bs[nb][so1] = sb1;
            __syncthreads();
        }
    }

    // epilogue: c-fragment layout: rows (lane>>2, +8), cols (lane&3)*2
    const int cr = bm + wm * 64 + (lane >> 2);
    const int cc = bn + wn * 32 + (lane & 3) * 2;
#pragma unroll
    for (int mi = 0; mi < 4; mi++) {
#pragma unroll
        for (int ni = 0; ni < 4; ni++) {
            float2 v0 = make_float2(acc[mi][ni][0], acc[mi][ni][1]);
            float2 v1 = make_float2(acc[mi][ni][2], acc[mi][ni][3]);
            *(float2*)&C[(size_t)(cr + mi * 16) * N + cc + ni * 8]     = v0;
            *(float2*)&C[(size_t)(cr + mi * 16 + 8) * N + cc + ni * 8] = v1;
        }
    }
}

// =========== split-convert: X[rows,HID] f32 -> Y[rows,3*HID] = [hi|lo|hi] ====
__global__ void conv_act(const float* __restrict__ X, __nv_bfloat16* __restrict__ Y)
{
    int idx = (blockIdx.x * blockDim.x + threadIdx.x) * 2;
    int r = idx / HID, k = idx % HID;
    float2 x = *(const float2*)(X + idx);
    __nv_bfloat16 h0 = __float2bfloat16(x.x);
    __nv_bfloat16 h1 = __float2bfloat16(x.y);
    __nv_bfloat16 l0 = __float2bfloat16(x.x - __bfloat162float(h0));
    __nv_bfloat16 l1 = __float2bfloat16(x.y - __bfloat162float(h1));
    __nv_bfloat162 hv; hv.x = h0; hv.y = h1;
    __nv_bfloat162 lv; lv.x = l0; lv.y = l1;
    size_t base = (size_t)r * K2 + k;
    *(__nv_bfloat162*)(Y + base)           = hv;
    *(__nv_bfloat162*)(Y + base + HID)     = lv;
    *(__nv_bfloat162*)(Y + base + 2 * HID) = hv;
}

// ==== transpose+split: W[HID,N] f32 -> Wt[N,3*HID] = [hi|hi|lo] ==============
__global__ void conv_wt(const float* __restrict__ W, __nv_bfloat16* __restrict__ Wt, int N)
{
    __shared__ float t[32][33];
    int n0 = blockIdx.x * 32, k0 = blockIdx.y * 32;
    int tx = threadIdx.x, ty0 = threadIdx.y;   // (32, 8)
#pragma unroll
    for (int i = 0; i < 4; i++) {
        int ty = ty0 + i * 8;
        t[ty][tx] = W[(size_t)(k0 + ty) * N + n0 + tx];
    }
    __syncthreads();
#pragma unroll
    for (int i = 0; i < 4; i++) {
        int n = n0 + ty0 + i * 8;
        int k = k0 + tx;
        float x = t[tx][ty0 + i * 8];
        __nv_bfloat16 hi = __float2bfloat16(x);
        __nv_bfloat16 lo = __float2bfloat16(x - __bfloat162float(hi));
        size_t b = (size_t)n * K2 + k;
        Wt[b]           = hi;
        Wt[b + HID]     = hi;
        Wt[b + 2 * HID] = lo;
    }
}

// -------- per-head RMSNorm + RoPE on Q (16 heads) and K (4 heads), in-place --
__global__ void norm_rope_kernel(const float* __restrict__ cosT,
                                 const float* __restrict__ sinT,
                                 const float* __restrict__ qscale,
                                 const float* __restrict__ kscale)
{
    int s = blockIdx.x;
    int h = blockIdx.y;
    int d = threadIdx.x;

    float* base;
    const float* sc;
    if (h < NH) { base = g_Q + (size_t)s * HID + h * HD;          sc = qscale; }
    else        { base = g_K + (size_t)s * (NKV*HD) + (h-NH)*HD;  sc = kscale; }

    float x = base[d];
    float v = x * x;
#pragma unroll
    for (int m = 16; m > 0; m >>= 1) v += __shfl_xor_sync(0xffffffffu, v, m);

    __shared__ float ws[4];
    __shared__ float rn[HD];
    if ((d & 31) == 0) ws[d >> 5] = v;
    __syncthreads();
    float tot = ws[0] + ws[1] + ws[2] + ws[3];
    float inv = rsqrtf(tot * (1.0f / HD) + EPSV);

    float r = x * inv * sc[d];
    rn[d] = r;
    __syncthreads();
    float rot = (d < 64) ? -rn[d + 64] : rn[d - 64];
    float c  = cosT[(size_t)s * HD + d];
    float sn = sinT[(size_t)s * HD + d];
    base[d] = r * c + rot * sn;
}

// ---------------- causal GQA flash attention, fp32 ---------------------------
#define QT_P 68
#define VS_P 132
#define ATT_SMEM_FLOATS (128*QT_P + 128*QT_P + 64*VS_P + 64*QT_P)

__global__ __launch_bounds__(256) void attn_kernel(float* __restrict__ O)
{
    extern __shared__ float sm[];
    float* QsT = sm;
    float* KsT = QsT + 128 * QT_P;
    float* Vs  = KsT + 128 * QT_P;
    float* Ps  = Vs  + 64  * VS_P;

    int qb = blockIdx.x, h = blockIdx.y;
    int kv = h >> 2;
    int t  = threadIdx.x;
    int rg = t >> 4, cg = t & 15;
    const float scale = 0.08838834764831845f;

    const float* Qb = g_Q + (size_t)(qb * 64) * HID + h * HD;
#pragma unroll
    for (int i = 0; i < 8; i++) {
        int idx = i * 256 + t;
        int r = idx >> 5, d4 = idx & 31;
        float4 q = *(const float4*)&Qb[(size_t)r * HID + d4 * 4];
        QsT[(d4*4 + 0) * QT_P + r] = q.x;
        QsT[(d4*4 + 1) * QT_P + r] = q.y;
        QsT[(d4*4 + 2) * QT_P + r] = q.z;
        QsT[(d4*4 + 3) * QT_P + r] = q.w;
    }

    float m[4], l[4], acc[4][8];
#pragma unroll
    for (int i = 0; i < 4; i++) {
        m[i] = -1e30f; l[i] = 0.0f;
#pragma unroll
        for (int dd = 0; dd < 8; dd++) acc[i][dd] = 0.0f;
    }

    for (int kb = 0; kb <= qb; kb++) {
        __syncthreads();
        const float* Kb = g_K + (size_t)(kb * 64) * (NKV*HD) + kv * HD;
        const float* Vb = g_V + (size_t)(kb * 64) * (NKV*HD) + kv * HD;
#pragma unroll
        for (int i = 0; i < 8; i++) {
            int idx = i * 256 + t;
            int r = idx >> 5, d4 = idx & 31;
            float4 kk = *(const float4*)&Kb[(size_t)r * (NKV*HD) + d4 * 4];
            KsT[(d4*4 + 0) * QT_P + r] = kk.x;
            KsT[(d4*4 + 1) * QT_P + r] = kk.y;
            KsT[(d4*4 + 2) * QT_P + r] = kk.z;
            KsT[(d4*4 + 3) * QT_P + r] = kk.w;
            float4 vv = *(const float4*)&Vb[(size_t)r * (NKV*HD) + d4 * 4];
            *(float4*)&Vs[r * VS_P + d4 * 4] = vv;
        }
        __syncthreads();

        float s[4][4];
#pragma unroll
        for (int i = 0; i < 4; i++)
#pragma unroll
            for (int j = 0; j < 4; j++) s[i][j] = 0.0f;
#pragma unroll 8
        for (int d = 0; d < 128; d++) {
            float4 qv = *(float4*)&QsT[d * QT_P + rg * 4];
            float4 kw = *(float4*)&KsT[d * QT_P + cg * 4];
            s[0][0] += qv.x * kw.x; s[0][1] += qv.x * kw.y; s[0][2] += qv.x * kw.z; s[0][3] += qv.x * kw.w;
            s[1][0] += qv.y * kw.x; s[1][1] += qv.y * kw.y; s[1][2] += qv.y * kw.z; s[1][3] += qv.y * kw.w;
            s[2][0] += qv.z * kw.x; s[2][1] += qv.z * kw.y; s[2][2] += qv.z * kw.z; s[2][3] += qv.z * kw.w;
            s[3][0] += qv.w * kw.x; s[3][1] += qv.w * kw.y; s[3][2] += qv.w * kw.z; s[3][3] += qv.w * kw.w;
        }
#pragma unroll
        for (int i = 0; i < 4; i++)
#pragma unroll
            for (int j = 0; j < 4; j++) s[i][j] *= scale;

        if (kb == qb) {
#pragma unroll
            for (int i = 0; i < 4; i++)
#pragma unroll
                for (int j = 0; j < 4; j++)
                    if (cg * 4 + j > rg * 4 + i) s[i][j] = -1e30f;
        }

        float rm[4];
#pragma unroll
        for (int i = 0; i < 4; i++)
            rm[i] = fmaxf(fmaxf(s[i][0], s[i][1]), fmaxf(s[i][2], s[i][3]));
#pragma unroll
        for (int msk = 8; msk > 0; msk >>= 1)
#pragma unroll
            for (int i = 0; i < 4; i++)
                rm[i] = fmaxf(rm[i], __shfl_xor_sync(0xffffffffu, rm[i], msk));

        float corr[4];
#pragma unroll
        for (int i = 0; i < 4; i++) {
            float nm = fmaxf(m[i], rm[i]);
            corr[i] = __expf(m[i] - nm);
            m[i] = nm;
        }

        float rs[4] = {0.f, 0.f, 0.f, 0.f};
#pragma unroll
        for (int i = 0; i < 4; i++)
#pragma unroll
            for (int j = 0; j < 4; j++) {
                float p = __expf(s[i][j] - m[i]);
                Ps[(rg * 4 + i) * QT_P + cg * 4 + j] = p;
                rs[i] += p;
            }
#pragma unroll
        for (int msk = 8; msk > 0; msk >>= 1)
#pragma unroll
            for (int i = 0; i < 4; i++)
                rs[i] += __shfl_xor_sync(0xffffffffu, rs[i], msk);
#pragma unroll
        for (int i = 0; i < 4; i++) {
            l[i] = l[i] * corr[i] + rs[i];
#pragma unroll
            for (int dd = 0; dd < 8; dd++) acc[i][dd] *= corr[i];
        }
        __syncthreads();

#pragma unroll 4
        for (int j = 0; j < 64; j++) {
            float4 v0 = *(float4*)&Vs[j * VS_P + cg * 8];
            float4 v1 = *(float4*)&Vs[j * VS_P + cg * 8 + 4];
#pragma unroll
            for (int i = 0; i < 4; i++) {
                float p = Ps[(rg * 4 + i) * QT_P + j];
                acc[i][0] += p * v0.x; acc[i][1] += p * v0.y;
                acc[i][2] += p * v0.z; acc[i][3] += p * v0.w;
                acc[i][4] += p * v1.x; acc[i][5] += p * v1.y;
                acc[i][6] += p * v1.z; acc[i][7] += p * v1.w;
            }
        }
    }

    float* Ob = O + (size_t)(qb * 64) * HID + h * HD;
#pragma unroll
    for (int i = 0; i < 4; i++) {
        float invl = 1.0f / l[i];
        float4 o0 = make_float4(acc[i][0]*invl, acc[i][1]*invl, acc[i][2]*invl, acc[i][3]*invl);
        float4 o1 = make_float4(acc[i][4]*invl, acc[i][5]*invl, acc[i][6]*invl, acc[i][7]*invl);
        size_t row = (size_t)(rg * 4 + i);
        *(float4*)&Ob[row * HID + cg * 8]     = o0;
        *(float4*)&Ob[row * HID + cg * 8 + 4] = o1;
    }
}

// ---------------- final RMSNorm over hidden=2048 -----------------------------
__global__ void final_norm_kernel(const float* __restrict__ sc, float* __restrict__ out)
{
    int s = blockIdx.x;
    const float* y = g_Y + (size_t)s * HID;
    float v = 0.0f;
    for (int d = threadIdx.x; d < HID; d += 256) { float x = y[d]; v += x * x; }
#pragma unroll
    for (int m = 16; m > 0; m >>= 1) v += __shfl_xor_sync(0xffffffffu, v, m);
    __shared__ float ws[8];
    if ((threadIdx.x & 31) == 0) ws[threadIdx.x >> 5] = v;
    __syncthreads();
    float tot = 0.0f;
#pragma unroll
    for (int i = 0; i < 8; i++) tot += ws[i];
    float inv = rsqrtf(tot * (1.0f / HID) + EPSV);
    for (int d = threadIdx.x; d < HID; d += 256)
        out[(size_t)s * HID + d] = y[d] * inv * sc[d];
}

// ---------------- launch -----------------------------------------------------
extern "C" void kernel_launch(void* const* d_in, const int* in_sizes, int n_in,
                              void* d_out, int out_size)
{
    const float* hidden = (const float*)d_in[0];
    const float* cosT   = (const float*)d_in[1];
    const float* sinT   = (const float*)d_in[2];
    const float* Wq     = (const float*)d_in[3];
    const float* Wk     = (const float*)d_in[4];
    const float* Wv     = (const float*)d_in[5];
    const float* Wo     = (const float*)d_in[6];
    const float* qs     = (const float*)d_in[7];
    const float* ks     = (const float*)d_in[8];
    const float* ls     = (const float*)d_in[9];
    float* out = (float*)d_out;

    float *Qp, *Kp, *Vp, *AOp, *Yp;
    __nv_bfloat16 *A2p, *AO2p, *Wq2p, *Wk2p, *Wv2p, *Wo2p;
    cudaGetSymbolAddress((void**)&Qp,   g_Q);
    cudaGetSymbolAddress((void**)&Kp,   g_K);
    cudaGetSymbolAddress((void**)&Vp,   g_V);
    cudaGetSymbolAddress((void**)&AOp,  g_AO);
    cudaGetSymbolAddress((void**)&Yp,   g_Y);
    cudaGetSymbolAddress((void**)&A2p,  g_A2);
    cudaGetSymbolAddress((void**)&AO2p, g_AO2);
    cudaGetSymbolAddress((void**)&Wq2p, g_Wq2);
    cudaGetSymbolAddress((void**)&Wk2p, g_Wk2);
    cudaGetSymbolAddress((void**)&Wv2p, g_Wv2);
    cudaGetSymbolAddress((void**)&Wo2p, g_Wo2);

    cudaFuncSetAttribute(attn_kernel, cudaFuncAttributeMaxDynamicSharedMemorySize,
                         ATT_SMEM_FLOATS * 4);

    // split-convert activations + weights
    conv_act<<<SEQ * HID / 512, 256>>>(hidden, A2p);
    conv_wt<<<dim3(HID / 32, HID / 32), dim3(32, 8)>>>(Wq, Wq2p, HID);
    conv_wt<<<dim3((NKV*HD) / 32, HID / 32), dim3(32, 8)>>>(Wk, Wk2p, NKV * HD);
    conv_wt<<<dim3((NKV*HD) / 32, HID / 32), dim3(32, 8)>>>(Wv, Wv2p, NKV * HD);
    conv_wt<<<dim3(HID / 32, HID / 32), dim3(32, 8)>>>(Wo, Wo2p, HID);

    // QKV projections on tensor cores (legacy HMMA path)
    gemm_mma<<<dim3(HID / 128, SEQ / 128), 256>>>(A2p, Wq2p, Qp, HID);
    gemm_mma<<<dim3((NKV*HD) / 128, SEQ / 128), 256>>>(A2p, Wk2p, Kp, NKV * HD);
    gemm_mma<<<dim3((NKV*HD) / 128, SEQ / 128), 256>>>(A2p, Wv2p, Vp, NKV * HD);

    // per-head RMSNorm + RoPE
    norm_rope_kernel<<<dim3(SEQ, NH + NKV), HD>>>(cosT, sinT, qs, ks);

    // causal GQA attention (fp32)
    attn_kernel<<<dim3(SEQ / 64, NH), 256, ATT_SMEM_FLOATS * 4>>>(AOp);

    // output projection on tensor cores
    conv_act<<<SEQ * HID / 512, 256>>>(AOp, AO2p);
    gemm_mma<<<dim3(HID / 128, SEQ / 128), 256>>>(AO2p, Wo2p, Yp, HID);

    // final RMSNorm -> d_out
    final_norm_kernel<<<SEQ, 256>>>(ls, out);
}

// round 4
// speedup vs baseline: 2.9124x; 2.9124x over previous
#include <cuda_runtime.h>
#include <cuda_bf16.h>
#include <cstdint>
#include <math.h>

#define SEQ 2048
#define HID 2048
#define HD  128
#define NH  16
#define NKV 4
#define KVW (NKV*HD)           // 512
#define EPSV 1e-6f
#define K2  (3 * HID)          // 6144 = [hi | lo | hi] concat along K
#define BKG 64
#define NSTG 3
#define NC2 (K2 / BKG)         // 96
#define GP  72                 // gemm smem row stride (bf16 elems)

// ---------------- scratch (static device globals; no allocation) -------------
__device__ float g_Q[SEQ * HID];
__device__ float g_K[SEQ * KVW];
__device__ float g_V[SEQ * KVW];
__device__ float g_AO[SEQ * HID];
__device__ float g_Y[SEQ * HID];

__device__ __nv_bfloat16 g_A2[SEQ * K2];
__device__ __nv_bfloat16 g_AO2[SEQ * K2];
__device__ __nv_bfloat16 g_Wq2[HID * K2];
__device__ __nv_bfloat16 g_Wk2[KVW * K2];
__device__ __nv_bfloat16 g_Wv2[KVW * K2];
__device__ __nv_bfloat16 g_Wo2[HID * K2];

__device__ __nv_bfloat16 g_Qh[SEQ * HID];
__device__ __nv_bfloat16 g_Ql[SEQ * HID];
__device__ __nv_bfloat16 g_Kh[SEQ * KVW];
__device__ __nv_bfloat16 g_Kl[SEQ * KVW];
__device__ __nv_bfloat16 g_Vh[SEQ * KVW];
__device__ __nv_bfloat16 g_Vl[SEQ * KVW];

// ======================= helpers =============================================
__device__ __forceinline__ uint32_t smem_u32(const void* p) {
    uint32_t a;
    asm("{ .reg .u64 t; cvta.to.shared.u64 t, %1; cvt.u32.u64 %0, t; }" : "=r"(a) : "l"(p));
    return a;
}
__device__ __forceinline__ void ldsm4(uint32_t* r, uint32_t addr) {
    asm volatile("ldmatrix.sync.aligned.m8n8.x4.shared.b16 {%0,%1,%2,%3}, [%4];"
        : "=r"(r[0]), "=r"(r[1]), "=r"(r[2]), "=r"(r[3]) : "r"(addr));
}
__device__ __forceinline__ void ldsm4t(uint32_t* r, uint32_t addr) {
    asm volatile("ldmatrix.sync.aligned.m8n8.x4.trans.shared.b16 {%0,%1,%2,%3}, [%4];"
        : "=r"(r[0]), "=r"(r[1]), "=r"(r[2]), "=r"(r[3]) : "r"(addr));
}
__device__ __forceinline__ void mma16816(float* c, const uint32_t* a, const uint32_t* b) {
    asm volatile(
        "mma.sync.aligned.m16n8k16.row.col.f32.bf16.bf16.f32 "
        "{%0,%1,%2,%3}, {%4,%5,%6,%7}, {%8,%9}, {%0,%1,%2,%3};"
        : "+f"(c[0]), "+f"(c[1]), "+f"(c[2]), "+f"(c[3])
        : "r"(a[0]), "r"(a[1]), "r"(a[2]), "r"(a[3]), "r"(b[0]), "r"(b[1]));
}
__device__ __forceinline__ void cpa16(void* s, const void* g) {
    uint32_t sa = smem_u32(s);
    asm volatile("cp.async.cg.shared.global [%0], [%1], 16;" :: "r"(sa), "l"(g));
}
__device__ __forceinline__ uint32_t packbf(float a, float b) {
    __nv_bfloat162 t = __floats2bfloat162_rn(a, b);
    return *(uint32_t*)&t;
}

// ===== bf16 HMMA GEMM, cp.async 3-stage: C[M,N] f32 = A[M,K2] @ B[N,K2]^T ====
__global__ __launch_bounds__(256) void gemm_mma(const __nv_bfloat16* __restrict__ A,
                                                const __nv_bfloat16* __restrict__ B,
                                                float* __restrict__ C, int N)
{
    extern __shared__ char dynsm[];
    __nv_bfloat16* gs = (__nv_bfloat16*)dynsm;

    const int tid  = threadIdx.x;
    const int wid  = tid >> 5, lane = tid & 31;
    const int wm   = wid & 1, wn = wid >> 1;
    const int bm   = blockIdx.y * 128, bn = blockIdx.x * 128;
    const uint32_t sbase = smem_u32(gs);

#define ISSUE(c) do {                                                                   \
    int _k0 = (c) * BKG;                                                                \
    __nv_bfloat16* _sA = gs + ((c) % NSTG) * (2 * 128 * GP);                            \
    __nv_bfloat16* _sB = _sA + 128 * GP;                                                \
    _Pragma("unroll")                                                                   \
    for (int _i = 0; _i < 4; _i++) {                                                    \
        int _id = _i * 256 + tid; int _r = _id >> 3, _u = _id & 7;                      \
        cpa16(_sA + _r * GP + _u * 8, A + (size_t)(bm + _r) * K2 + _k0 + _u * 8);       \
    }                                                                                   \
    _Pragma("unroll")                                                                   \
    for (int _i = 0; _i < 4; _i++) {                                                    \
        int _id = _i * 256 + tid; int _r = _id >> 3, _u = _id & 7;                      \
        cpa16(_sB + _r * GP + _u * 8, B + (size_t)(bn + _r) * K2 + _k0 + _u * 8);       \
    }                                                                                   \
    asm volatile("cp.async.commit_group;" ::: "memory");                                \
} while (0)

    float acc[4][4][4];
#pragma unroll
    for (int i = 0; i < 4; i++)
#pragma unroll
        for (int j = 0; j < 4; j++)
#pragma unroll
            for (int k = 0; k < 4; k++) acc[i][j][k] = 0.0f;

    ISSUE(0);
    ISSUE(1);

    const uint32_t aOff = (uint32_t)((wm * 64 + (lane & 15)) * GP + ((lane >> 4) << 3)) * 2;
    const uint32_t bOff = (uint32_t)((wn * 32 + (lane & 7) + (((lane >> 4) & 1) << 3)) * GP
                                     + (((lane >> 3) & 1) << 3)) * 2;

    for (int c = 0; c < NC2; c++) {
        asm volatile("cp.async.wait_group 1;" ::: "memory");
        __syncthreads();
        if (c + 2 < NC2) { ISSUE(c + 2); }
        else { asm volatile("cp.async.commit_group;" ::: "memory"); }

        const uint32_t aB = sbase + (c % NSTG) * (2 * 128 * GP * 2);
        const uint32_t bB = aB + 128 * GP * 2;
#pragma unroll
        for (int ks = 0; ks < 4; ks++) {
            uint32_t af[4][4], bfr[2][4];
#pragma unroll
            for (int mi = 0; mi < 4; mi++)
                ldsm4(af[mi], aB + aOff + mi * (16 * GP * 2) + ks * 32);
#pragma unroll
            for (int nj = 0; nj < 2; nj++)
                ldsm4(bfr[nj], bB + bOff + nj * (16 * GP * 2) + ks * 32);
#pragma unroll
            for (int mi = 0; mi < 4; mi++)
#pragma unroll
                for (int ni = 0; ni < 4; ni++)
                    mma16816(acc[mi][ni], af[mi], &bfr[ni >> 1][(ni & 1) * 2]);
        }
    }
#undef ISSUE

    const int cr = bm + wm * 64 + (lane >> 2);
    const int cc = bn + wn * 32 + (lane & 3) * 2;
#pragma unroll
    for (int mi = 0; mi < 4; mi++) {
#pragma unroll
        for (int ni = 0; ni < 4; ni++) {
            float2 v0 = make_float2(acc[mi][ni][0], acc[mi][ni][1]);
            float2 v1 = make_float2(acc[mi][ni][2], acc[mi][ni][3]);
            *(float2*)&C[(size_t)(cr + mi * 16) * N + cc + ni * 8]     = v0;
            *(float2*)&C[(size_t)(cr + mi * 16 + 8) * N + cc + ni * 8] = v1;
        }
    }
}

// =========== split-convert: X[rows,HID] f32 -> Y[rows,3*HID] = [hi|lo|hi] ====
__global__ void conv_act(const float* __restrict__ X, __nv_bfloat16* __restrict__ Y)
{
    int idx = (blockIdx.x * blockDim.x + threadIdx.x) * 2;
    int r = idx / HID, k = idx % HID;
    float2 x = *(const float2*)(X + idx);
    __nv_bfloat16 h0 = __float2bfloat16(x.x);
    __nv_bfloat16 h1 = __float2bfloat16(x.y);
    __nv_bfloat16 l0 = __float2bfloat16(x.x - __bfloat162float(h0));
    __nv_bfloat16 l1 = __float2bfloat16(x.y - __bfloat162float(h1));
    __nv_bfloat162 hv; hv.x = h0; hv.y = h1;
    __nv_bfloat162 lv; lv.x = l0; lv.y = l1;
    size_t base = (size_t)r * K2 + k;
    *(__nv_bfloat162*)(Y + base)           = hv;
    *(__nv_bfloat162*)(Y + base + HID)     = lv;
    *(__nv_bfloat162*)(Y + base + 2 * HID) = hv;
}

// ==== transpose+split: W[HID,N] f32 -> Wt[N,3*HID] = [hi|hi|lo] ==============
__global__ void conv_wt(const float* __restrict__ W, __nv_bfloat16* __restrict__ Wt, int N)
{
    __shared__ float t[32][33];
    int n0 = blockIdx.x * 32, k0 = blockIdx.y * 32;
    int tx = threadIdx.x, ty0 = threadIdx.y;   // (32, 8)
#pragma unroll
    for (int i = 0; i < 4; i++) {
        int ty = ty0 + i * 8;
        t[ty][tx] = W[(size_t)(k0 + ty) * N + n0 + tx];
    }
    __syncthreads();
#pragma unroll
    for (int i = 0; i < 4; i++) {
        int n = n0 + ty0 + i * 8;
        int k = k0 + tx;
        float x = t[tx][ty0 + i * 8];
        __nv_bfloat16 hi = __float2bfloat16(x);
        __nv_bfloat16 lo = __float2bfloat16(x - __bfloat162float(hi));
        size_t b = (size_t)n * K2 + k;
        Wt[b]           = hi;
        Wt[b + HID]     = hi;
        Wt[b + 2 * HID] = lo;
    }
}

// -------- per-head RMSNorm+RoPE on Q/K (writes bf16 splits); V split only ----
__global__ void norm_rope_kernel(const float* __restrict__ cosT,
                                 const float* __restrict__ sinT,
                                 const float* __restrict__ qscale,
                                 const float* __restrict__ kscale)
{
    int s = blockIdx.x;
    int h = blockIdx.y;   // 0..15 Q, 16..19 K, 20..23 V
    int d = threadIdx.x;  // 0..127

    if (h >= NH + NKV) {  // V: split only
        int i = (size_t)0 + s * KVW + (h - NH - NKV) * HD + d;
        float x = g_V[i];
        __nv_bfloat16 hi = __float2bfloat16(x);
        g_Vh[i] = hi;
        g_Vl[i] = __float2bfloat16(x - __bfloat162float(hi));
        return;
    }

    const float* base;
    const float* sc;
    size_t oidx;
    if (h < NH) { base = g_Q + (size_t)s * HID + h * HD; sc = qscale;
                  oidx = (size_t)s * HID + h * HD + d; }
    else        { base = g_K + (size_t)s * KVW + (h - NH) * HD; sc = kscale;
                  oidx = (size_t)s * KVW + (h - NH) * HD + d; }

    float x = base[d];
    float v = x * x;
#pragma unroll
    for (int m = 16; m > 0; m >>= 1) v += __shfl_xor_sync(0xffffffffu, v, m);

    __shared__ float ws[4];
    __shared__ float rn[HD];
    if ((d & 31) == 0) ws[d >> 5] = v;
    __syncthreads();
    float tot = ws[0] + ws[1] + ws[2] + ws[3];
    float inv = rsqrtf(tot * (1.0f / HD) + EPSV);

    float r = x * inv * sc[d];
    rn[d] = r;
    __syncthreads();
    float rot = (d < 64) ? -rn[d + 64] : rn[d - 64];
    float c  = cosT[(size_t)s * HD + d];
    float sn = sinT[(size_t)s * HD + d];
    float out = r * c + rot * sn;

    __nv_bfloat16 hi = __float2bfloat16(out);
    __nv_bfloat16 lo = __float2bfloat16(out - __bfloat162float(hi));
    if (h < NH) { g_Qh[oidx] = hi; g_Ql[oidx] = lo; }
    else        { g_Kh[oidx] = hi; g_Kl[oidx] = lo; }
}

// ---------------- causal GQA flash attention, HMMA + Ootomo splits -----------
// 128 threads = 4 warps; block = 64 q-rows x 1 head; warp w owns rows 16w..16w+15.
#define AP 136
#define ATT_SMEM (6 * 64 * AP * 2)

__global__ __launch_bounds__(128) void attn_mma(float* __restrict__ O)
{
    extern __shared__ char dynsm[];
    __nv_bfloat16* sm = (__nv_bfloat16*)dynsm;
    __nv_bfloat16* Qh = sm;
    __nv_bfloat16* Ql = sm + 1 * 64 * AP;
    __nv_bfloat16* Kh = sm + 2 * 64 * AP;
    __nv_bfloat16* Kl = sm + 3 * 64 * AP;
    __nv_bfloat16* Vh = sm + 4 * 64 * AP;
    __nv_bfloat16* Vl = sm + 5 * 64 * AP;

    const int qb = 31 - blockIdx.x;      // big blocks first
    const int h  = blockIdx.y;
    const int kv = h >> 2;
    const int tid = threadIdx.x, w = tid >> 5, l = tid & 31;
    const float scl = 0.08838834764831845f;

    // load Q tiles (64 rows x 128 d, bf16 splits)
    {
        const __nv_bfloat16* gh = g_Qh + (size_t)(qb * 64) * HID + h * HD;
        const __nv_bfloat16* gl = g_Ql + (size_t)(qb * 64) * HID + h * HD;
#pragma unroll
        for (int i = 0; i < 8; i++) {
            int id = i * 128 + tid;
            int r = id >> 4, u = id & 15;
            *(uint4*)(Qh + r * AP + u * 8) = *(const uint4*)(gh + (size_t)r * HID + u * 8);
            *(uint4*)(Ql + r * AP + u * 8) = *(const uint4*)(gl + (size_t)r * HID + u * 8);
        }
    }

    const uint32_t qa  = smem_u32(Qh), qla = smem_u32(Ql);
    const uint32_t kha = smem_u32(Kh), kla = smem_u32(Kl);
    const uint32_t vha = smem_u32(Vh), vla = smem_u32(Vl);
    const uint32_t aOff = (uint32_t)((w * 16 + (l & 15)) * AP + ((l >> 4) << 3)) * 2;

    float m0 = -1e30f, m1 = -1e30f, ls0 = 0.0f, ls1 = 0.0f;
    float accO[16][4];
#pragma unroll
    for (int i = 0; i < 16; i++)
#pragma unroll
        for (int j = 0; j < 4; j++) accO[i][j] = 0.0f;

    for (int kb = 0; kb <= qb; kb++) {
        __syncthreads();
        {
            const __nv_bfloat16* gkh = g_Kh + (size_t)(kb * 64) * KVW + kv * HD;
            const __nv_bfloat16* gkl = g_Kl + (size_t)(kb * 64) * KVW + kv * HD;
            const __nv_bfloat16* gvh = g_Vh + (size_t)(kb * 64) * KVW + kv * HD;
            const __nv_bfloat16* gvl = g_Vl + (size_t)(kb * 64) * KVW + kv * HD;
#pragma unroll
            for (int i = 0; i < 8; i++) {
                int id = i * 128 + tid;
                int r = id >> 4, u = id & 15;
                *(uint4*)(Kh + r * AP + u * 8) = *(const uint4*)(gkh + (size_t)r * KVW + u * 8);
                *(uint4*)(Kl + r * AP + u * 8) = *(const uint4*)(gkl + (size_t)r * KVW + u * 8);
                *(uint4*)(Vh + r * AP + u * 8) = *(const uint4*)(gvh + (size_t)r * KVW + u * 8);
                *(uint4*)(Vl + r * AP + u * 8) = *(const uint4*)(gvl + (size_t)r * KVW + u * 8);
            }
        }
        __syncthreads();

        // ---- S = (Qh·Kh + Ql·Kh + Qh·Kl) ----
        float S[8][4];
#pragma unroll
        for (int t = 0; t < 8; t++)
#pragma unroll
            for (int e = 0; e < 4; e++) S[t][e] = 0.0f;

#pragma unroll
        for (int pass = 0; pass < 3; pass++) {
            const uint32_t Ab = (pass == 1) ? qla : qa;
            const uint32_t Bb = (pass == 2) ? kla : kha;
#pragma unroll
            for (int ks = 0; ks < 8; ks++) {
                uint32_t af[4], bfr[4][4];
                ldsm4(af, Ab + aOff + ks * 32);
#pragma unroll
                for (int g = 0; g < 4; g++)
                    ldsm4(bfr[g], Bb + (uint32_t)((g * 16 + (l & 7) + (((l >> 4) & 1) << 3)) * AP
                                                  + (((l >> 3) & 1) << 3)) * 2 + ks * 32);
#pragma unroll
                for (int t = 0; t < 8; t++)
                    mma16816(S[t], af, &bfr[t >> 1][(t & 1) * 2]);
            }
        }

        // scale + causal mask
#pragma unroll
        for (int t = 0; t < 8; t++)
#pragma unroll
            for (int e = 0; e < 4; e++) S[t][e] *= scl;
        if (kb == qb) {
            int r0 = (l >> 2) + 16 * w, r1 = r0 + 8;
#pragma unroll
            for (int t = 0; t < 8; t++) {
                int cb = t * 8 + (l & 3) * 2;
                if (cb     > r0) S[t][0] = -1e30f;
                if (cb + 1 > r0) S[t][1] = -1e30f;
                if (cb     > r1) S[t][2] = -1e30f;
                if (cb + 1 > r1) S[t][3] = -1e30f;
            }
        }

        // row max
        float mx0 = -1e30f, mx1 = -1e30f;
#pragma unroll
        for (int t = 0; t < 8; t++) {
            mx0 = fmaxf(mx0, fmaxf(S[t][0], S[t][1]));
            mx1 = fmaxf(mx1, fmaxf(S[t][2], S[t][3]));
        }
        mx0 = fmaxf(mx0, __shfl_xor_sync(0xffffffffu, mx0, 1));
        mx0 = fmaxf(mx0, __shfl_xor_sync(0xffffffffu, mx0, 2));
        mx1 = fmaxf(mx1, __shfl_xor_sync(0xffffffffu, mx1, 1));
        mx1 = fmaxf(mx1, __shfl_xor_sync(0xffffffffu, mx1, 2));

        float nm0 = fmaxf(m0, mx0), nm1 = fmaxf(m1, mx1);
        float cr0 = __expf(m0 - nm0), cr1 = __expf(m1 - nm1);
        m0 = nm0; m1 = nm1;
        ls0 *= cr0; ls1 *= cr1;
#pragma unroll
        for (int t = 0; t < 16; t++) {
            accO[t][0] *= cr0; accO[t][1] *= cr0;
            accO[t][2] *= cr1; accO[t][3] *= cr1;
        }

        // P = exp(S - m), split into Ph + Pl (register A-fragments)
        uint32_t Pha[4][4], Pla[4][4];
        float rs0 = 0.0f, rs1 = 0.0f;
#pragma unroll
        for (int t = 0; t < 8; t++) {
            float p0 = __expf(S[t][0] - nm0), p1 = __expf(S[t][1] - nm0);
            float p2 = __expf(S[t][2] - nm1), p3 = __expf(S[t][3] - nm1);
            rs0 += p0 + p1; rs1 += p2 + p3;
            __nv_bfloat16 b0 = __float2bfloat16(p0), b1 = __float2bfloat16(p1);
            __nv_bfloat16 b2 = __float2bfloat16(p2), b3 = __float2bfloat16(p3);
            uint32_t ph01 = packbf(__bfloat162float(b0), __bfloat162float(b1));
            uint32_t ph23 = packbf(__bfloat162float(b2), __bfloat162float(b3));
            // exact hi re-pack (values already bf16-rounded; packbf re-round is identity)
            uint32_t pl01 = packbf(p0 - __bfloat162float(b0), p1 - __bfloat162float(b1));
            uint32_t pl23 = packbf(p2 - __bfloat162float(b2), p3 - __bfloat162float(b3));
            int kc = t >> 1, hi = (t & 1) * 2;
            Pha[kc][hi]     = ph01;
            Pha[kc][hi + 1] = ph23;
            Pla[kc][hi]     = pl01;
            Pla[kc][hi + 1] = pl23;
        }
        rs0 += __shfl_xor_sync(0xffffffffu, rs0, 1);
        rs0 += __shfl_xor_sync(0xffffffffu, rs0, 2);
        rs1 += __shfl_xor_sync(0xffffffffu, rs1, 1);
        rs1 += __shfl_xor_sync(0xffffffffu, rs1, 2);
        ls0 += rs0; ls1 += rs1;

        // ---- PV: acc += Ph·Vh + Pl·Vh + Ph·Vl ----
#pragma unroll
        for (int kc = 0; kc < 4; kc++) {
            uint32_t vb[8][4];
#pragma unroll
            for (int g = 0; g < 8; g++)
                ldsm4t(vb[g], vha + (uint32_t)((kc * 16 + (l & 15)) * AP
                                               + (g * 16 + ((l >> 4) << 3))) * 2);
#pragma unroll
            for (int nd = 0; nd < 16; nd++)
                mma16816(accO[nd], Pha[kc], &vb[nd >> 1][(nd & 1) * 2]);
#pragma unroll
            for (int nd = 0; nd < 16; nd++)
                mma16816(accO[nd], Pla[kc], &vb[nd >> 1][(nd & 1) * 2]);
#pragma unroll
            for (int g = 0; g < 8; g++)
                ldsm4t(vb[g], vla + (uint32_t)((kc * 16 + (l & 15)) * AP
                                               + (g * 16 + ((l >> 4) << 3))) * 2);
#pragma unroll
            for (int nd = 0; nd < 16; nd++)
                mma16816(accO[nd], Pha[kc], &vb[nd >> 1][(nd & 1) * 2]);
        }
    }

    // write out
    float inv0 = 1.0f / ls0, inv1 = 1.0f / ls1;
    float* Ob = O + (size_t)(qb * 64 + w * 16) * HID + h * HD;
    int r0 = l >> 2, cc = (l & 3) * 2;
#pragma unroll
    for (int nd = 0; nd < 16; nd++) {
        float2 v0 = make_float2(accO[nd][0] * inv0, accO[nd][1] * inv0);
        float2 v1 = make_float2(accO[nd][2] * inv1, accO[nd][3] * inv1);
        *(float2*)&Ob[(size_t)r0 * HID + nd * 8 + cc]       = v0;
        *(float2*)&Ob[(size_t)(r0 + 8) * HID + nd * 8 + cc] = v1;
    }
}

// ---------------- final RMSNorm over hidden=2048 -----------------------------
__global__ void final_norm_kernel(const float* __restrict__ sc, float* __restrict__ out)
{
    int s = blockIdx.x;
    const float* y = g_Y + (size_t)s * HID;
    float v = 0.0f;
    for (int d = threadIdx.x; d < HID; d += 256) { float x = y[d]; v += x * x; }
#pragma unroll
    for (int m = 16; m > 0; m >>= 1) v += __shfl_xor_sync(0xffffffffu, v, m);
    __shared__ float ws[8];
    if ((threadIdx.x & 31) == 0) ws[threadIdx.x >> 5] = v;
    __syncthreads();
    float tot = 0.0f;
#pragma unroll
    for (int i = 0; i < 8; i++) tot += ws[i];
    float inv = rsqrtf(tot * (1.0f / HID) + EPSV);
    for (int d = threadIdx.x; d < HID; d += 256)
        out[(size_t)s * HID + d] = y[d] * inv * sc[d];
}

// ---------------- launch -----------------------------------------------------
#define GEMM_SMEM (NSTG * 2 * 128 * GP * 2)

extern "C" void kernel_launch(void* const* d_in, const int* in_sizes, int n_in,
                              void* d_out, int out_size)
{
    const float* hidden = (const float*)d_in[0];
    const float* cosT   = (const float*)d_in[1];
    const float* sinT   = (const float*)d_in[2];
    const float* Wq     = (const float*)d_in[3];
    const float* Wk     = (const float*)d_in[4];
    const float* Wv     = (const float*)d_in[5];
    const float* Wo     = (const float*)d_in[6];
    const float* qs     = (const float*)d_in[7];
    const float* ks     = (const float*)d_in[8];
    const float* ls     = (const float*)d_in[9];
    float* out = (float*)d_out;

    float *Qp, *Kp, *Vp, *AOp, *Yp;
    __nv_bfloat16 *A2p, *AO2p, *Wq2p, *Wk2p, *Wv2p, *Wo2p;
    cudaGetSymbolAddress((void**)&Qp,   g_Q);
    cudaGetSymbolAddress((void**)&Kp,   g_K);
    cudaGetSymbolAddress((void**)&Vp,   g_V);
    cudaGetSymbolAddress((void**)&AOp,  g_AO);
    cudaGetSymbolAddress((void**)&Yp,   g_Y);
    cudaGetSymbolAddress((void**)&A2p,  g_A2);
    cudaGetSymbolAddress((void**)&AO2p, g_AO2);
    cudaGetSymbolAddress((void**)&Wq2p, g_Wq2);
    cudaGetSymbolAddress((void**)&Wk2p, g_Wk2);
    cudaGetSymbolAddress((void**)&Wv2p, g_Wv2);
    cudaGetSymbolAddress((void**)&Wo2p, g_Wo2);

    cudaFuncSetAttribute(gemm_mma, cudaFuncAttributeMaxDynamicSharedMemorySize, GEMM_SMEM);
    cudaFuncSetAttribute(attn_mma, cudaFuncAttributeMaxDynamicSharedMemorySize, ATT_SMEM);

    // split-convert activations + weights
    conv_act<<<SEQ * HID / 512, 256>>>(hidden, A2p);
    conv_wt<<<dim3(HID / 32, HID / 32), dim3(32, 8)>>>(Wq, Wq2p, HID);
    conv_wt<<<dim3(KVW / 32, HID / 32), dim3(32, 8)>>>(Wk, Wk2p, KVW);
    conv_wt<<<dim3(KVW / 32, HID / 32), dim3(32, 8)>>>(Wv, Wv2p, KVW);
    conv_wt<<<dim3(HID / 32, HID / 32), dim3(32, 8)>>>(Wo, Wo2p, HID);

    // QKV projections (HMMA, cp.async pipeline)
    gemm_mma<<<dim3(HID / 128, SEQ / 128), 256, GEMM_SMEM>>>(A2p, Wq2p, Qp, HID);
    gemm_mma<<<dim3(KVW / 128, SEQ / 128), 256, GEMM_SMEM>>>(A2p, Wk2p, Kp, KVW);
    gemm_mma<<<dim3(KVW / 128, SEQ / 128), 256, GEMM_SMEM>>>(A2p, Wv2p, Vp, KVW);

    // per-head RMSNorm + RoPE + bf16 splits (Q,K) and V split
    norm_rope_kernel<<<dim3(SEQ, NH + NKV + NKV), HD>>>(cosT, sinT, qs, ks);

    // causal GQA attention (HMMA, full splits)
    attn_mma<<<dim3(SEQ / 64, NH), 128, ATT_SMEM>>>(AOp);

    // output projection
    conv_act<<<SEQ * HID / 512, 256>>>(AOp, AO2p);
    gemm_mma<<<dim3(HID / 128, SEQ / 128), 256, GEMM_SMEM>>>(AO2p, Wo2p, Yp, HID);

    // final RMSNorm -> d_out
    final_norm_kernel<<<SEQ, 256>>>(ls, out);
}

// round 5
// speedup vs baseline: 2.9964x; 1.0288x over previous
#include <cuda_runtime.h>
#include <cuda_bf16.h>
#include <cstdint>
#include <math.h>

#define SEQ 2048
#define HID 2048
#define HD  128
#define NH  16
#define NKV 4
#define KVW (NKV*HD)           // 512
#define NQKV (HID + 2*KVW)     // 3072
#define EPSV 1e-6f
#define K2  (3 * HID)          // 6144 = [hi | lo | hi] along K
#define BKG 64
#define NSTG 4
#define NC2 (K2 / BKG)         // 96
#define GP  72                 // gemm smem row stride (bf16)

// ---------------- scratch ----------------------------------------------------
__device__ float g_Q[SEQ * HID];
__device__ float g_K[SEQ * KVW];
__device__ float g_V[SEQ * KVW];
__device__ float g_Y[SEQ * HID];

__device__ __nv_bfloat16 g_A2[SEQ * K2];
__device__ __nv_bfloat16 g_AO2[SEQ * K2];
__device__ __nv_bfloat16 g_Wqkv2[NQKV * K2];     // [Q rows | K rows | V rows]
__device__ __nv_bfloat16 g_Wo2[HID * K2];

__device__ __nv_bfloat16 g_Qh[SEQ * HID];
__device__ __nv_bfloat16 g_Ql[SEQ * HID];
__device__ __nv_bfloat16 g_Kh[SEQ * KVW];
__device__ __nv_bfloat16 g_Kl[SEQ * KVW];
__device__ __nv_bfloat16 g_Vh[SEQ * KVW];
__device__ __nv_bfloat16 g_Vl[SEQ * KVW];

// ======================= helpers =============================================
__device__ __forceinline__ uint32_t smem_u32(const void* p) {
    uint32_t a;
    asm("{ .reg .u64 t; cvta.to.shared.u64 t, %1; cvt.u32.u64 %0, t; }" : "=r"(a) : "l"(p));
    return a;
}
__device__ __forceinline__ void ldsm4(uint32_t* r, uint32_t addr) {
    asm volatile("ldmatrix.sync.aligned.m8n8.x4.shared.b16 {%0,%1,%2,%3}, [%4];"
        : "=r"(r[0]), "=r"(r[1]), "=r"(r[2]), "=r"(r[3]) : "r"(addr));
}
__device__ __forceinline__ void ldsm4t(uint32_t* r, uint32_t addr) {
    asm volatile("ldmatrix.sync.aligned.m8n8.x4.trans.shared.b16 {%0,%1,%2,%3}, [%4];"
        : "=r"(r[0]), "=r"(r[1]), "=r"(r[2]), "=r"(r[3]) : "r"(addr));
}
__device__ __forceinline__ void mma16816(float* c, const uint32_t* a, const uint32_t* b) {
    asm volatile(
        "mma.sync.aligned.m16n8k16.row.col.f32.bf16.bf16.f32 "
        "{%0,%1,%2,%3}, {%4,%5,%6,%7}, {%8,%9}, {%0,%1,%2,%3};"
        : "+f"(c[0]), "+f"(c[1]), "+f"(c[2]), "+f"(c[3])
        : "r"(a[0]), "r"(a[1]), "r"(a[2]), "r"(a[3]), "r"(b[0]), "r"(b[1]));
}
__device__ __forceinline__ void cpa16(void* s, const void* g) {
    uint32_t sa = smem_u32(s);
    asm volatile("cp.async.cg.shared.global [%0], [%1], 16;" :: "r"(sa), "l"(g));
}
__device__ __forceinline__ uint32_t packbf(float a, float b) {
    __nv_bfloat162 t = __floats2bfloat162_rn(a, b);
    return *(uint32_t*)&t;
}

// ===== bf16 HMMA GEMM core (4-stage cp.async). Returns acc in-place. =========
struct GemmAcc { float a[4][4][4]; };

__device__ __forceinline__ void gemm_core(const __nv_bfloat16* __restrict__ A,
                                          const __nv_bfloat16* __restrict__ B,
                                          int bm, int bn, __nv_bfloat16* gs,
                                          GemmAcc& G)
{
    const int tid  = threadIdx.x;
    const int wid  = tid >> 5, lane = tid & 31;
    const int wm   = wid & 1, wn = wid >> 1;
    const uint32_t sbase = smem_u32(gs);

#define ISSUE(c) do {                                                                   \
    int _k0 = (c) * BKG;                                                                \
    __nv_bfloat16* _sA = gs + ((c) % NSTG) * (2 * 128 * GP);                            \
    __nv_bfloat16* _sB = _sA + 128 * GP;                                                \
    _Pragma("unroll")                                                                   \
    for (int _i = 0; _i < 4; _i++) {                                                    \
        int _id = _i * 256 + tid; int _r = _id >> 3, _u = _id & 7;                      \
        cpa16(_sA + _r * GP + _u * 8, A + (size_t)(bm + _r) * K2 + _k0 + _u * 8);       \
    }                                                                                   \
    _Pragma("unroll")                                                                   \
    for (int _i = 0; _i < 4; _i++) {                                                    \
        int _id = _i * 256 + tid; int _r = _id >> 3, _u = _id & 7;                      \
        cpa16(_sB + _r * GP + _u * 8, B + (size_t)(bn + _r) * K2 + _k0 + _u * 8);       \
    }                                                                                   \
    asm volatile("cp.async.commit_group;" ::: "memory");                                \
} while (0)

#pragma unroll
    for (int i = 0; i < 4; i++)
#pragma unroll
        for (int j = 0; j < 4; j++)
#pragma unroll
            for (int k = 0; k < 4; k++) G.a[i][j][k] = 0.0f;

    ISSUE(0); ISSUE(1); ISSUE(2);

    const uint32_t aOff = (uint32_t)((wm * 64 + (lane & 15)) * GP + ((lane >> 4) << 3)) * 2;
    const uint32_t bOff = (uint32_t)((wn * 32 + (lane & 7) + (((lane >> 4) & 1) << 3)) * GP
                                     + (((lane >> 3) & 1) << 3)) * 2;

    for (int c = 0; c < NC2; c++) {
        asm volatile("cp.async.wait_group 2;" ::: "memory");
        __syncthreads();
        if (c + 3 < NC2) { ISSUE(c + 3); }
        else { asm volatile("cp.async.commit_group;" ::: "memory"); }

        const uint32_t aB = sbase + (c % NSTG) * (2 * 128 * GP * 2);
        const uint32_t bB = aB + 128 * GP * 2;
#pragma unroll
        for (int ks = 0; ks < 4; ks++) {
            uint32_t af[4][4], bfr[2][4];
#pragma unroll
            for (int mi = 0; mi < 4; mi++)
                ldsm4(af[mi], aB + aOff + mi * (16 * GP * 2) + ks * 32);
#pragma unroll
            for (int nj = 0; nj < 2; nj++)
                ldsm4(bfr[nj], bB + bOff + nj * (16 * GP * 2) + ks * 32);
#pragma unroll
            for (int mi = 0; mi < 4; mi++)
#pragma unroll
                for (int ni = 0; ni < 4; ni++)
                    mma16816(G.a[mi][ni], af[mi], &bfr[ni >> 1][(ni & 1) * 2]);
        }
    }
#undef ISSUE
}

// ---- fused QKV projection: B = g_Wqkv2, epilogue routes to g_Q/g_K/g_V ------
__global__ __launch_bounds__(256) void gemm_qkv()
{
    extern __shared__ char dynsm[];
    GemmAcc G;
    const int bm = blockIdx.y * 128, bn = blockIdx.x * 128;
    gemm_core(g_A2, g_Wqkv2, bm, bn, (__nv_bfloat16*)dynsm, G);

    float* Cb; int Nw, c0;
    if (bn < HID)            { Cb = g_Q; Nw = HID; c0 = bn; }
    else if (bn < HID + KVW) { Cb = g_K; Nw = KVW; c0 = bn - HID; }
    else                     { Cb = g_V; Nw = KVW; c0 = bn - HID - KVW; }

    const int lane = threadIdx.x & 31, wid = threadIdx.x >> 5;
    const int cr = bm + (wid & 1) * 64 + (lane >> 2);
    const int cc = c0 + (wid >> 1) * 32 + (lane & 3) * 2;
#pragma unroll
    for (int mi = 0; mi < 4; mi++)
#pragma unroll
        for (int ni = 0; ni < 4; ni++) {
            *(float2*)&Cb[(size_t)(cr + mi * 16) * Nw + cc + ni * 8] =
                make_float2(G.a[mi][ni][0], G.a[mi][ni][1]);
            *(float2*)&Cb[(size_t)(cr + mi * 16 + 8) * Nw + cc + ni * 8] =
                make_float2(G.a[mi][ni][2], G.a[mi][ni][3]);
        }
}

// ---- Wo projection: AO2 @ Wo2 -> g_Y ----------------------------------------
__global__ __launch_bounds__(256) void gemm_wo()
{
    extern __shared__ char dynsm[];
    GemmAcc G;
    const int bm = blockIdx.y * 128, bn = blockIdx.x * 128;
    gemm_core(g_AO2, g_Wo2, bm, bn, (__nv_bfloat16*)dynsm, G);

    const int lane = threadIdx.x & 31, wid = threadIdx.x >> 5;
    const int cr = bm + (wid & 1) * 64 + (lane >> 2);
    const int cc = bn + (wid >> 1) * 32 + (lane & 3) * 2;
#pragma unroll
    for (int mi = 0; mi < 4; mi++)
#pragma unroll
        for (int ni = 0; ni < 4; ni++) {
            *(float2*)&g_Y[(size_t)(cr + mi * 16) * HID + cc + ni * 8] =
                make_float2(G.a[mi][ni][0], G.a[mi][ni][1]);
            *(float2*)&g_Y[(size_t)(cr + mi * 16 + 8) * HID + cc + ni * 8] =
                make_float2(G.a[mi][ni][2], G.a[mi][ni][3]);
        }
}

// =========== split-convert hidden: f32 -> [hi|lo|hi] bf16 ====================
__global__ void conv_act(const float* __restrict__ X, __nv_bfloat16* __restrict__ Y)
{
    int idx = (blockIdx.x * blockDim.x + threadIdx.x) * 2;
    int r = idx / HID, k = idx % HID;
    float2 x = *(const float2*)(X + idx);
    __nv_bfloat16 h0 = __float2bfloat16(x.x);
    __nv_bfloat16 h1 = __float2bfloat16(x.y);
    __nv_bfloat16 l0 = __float2bfloat16(x.x - __bfloat162float(h0));
    __nv_bfloat16 l1 = __float2bfloat16(x.y - __bfloat162float(h1));
    __nv_bfloat162 hv; hv.x = h0; hv.y = h1;
    __nv_bfloat162 lv; lv.x = l0; lv.y = l1;
    size_t base = (size_t)r * K2 + k;
    *(__nv_bfloat162*)(Y + base)           = hv;
    *(__nv_bfloat162*)(Y + base + HID)     = lv;
    *(__nv_bfloat162*)(Y + base + 2 * HID) = hv;
}

// ==== transpose+split: W[HID,N] f32 -> Wt[N,3*HID] = [hi|hi|lo] ==============
__global__ void conv_wt(const float* __restrict__ W, __nv_bfloat16* __restrict__ Wt, int N)
{
    __shared__ float t[32][33];
    int n0 = blockIdx.x * 32, k0 = blockIdx.y * 32;
    int tx = threadIdx.x, ty0 = threadIdx.y;
#pragma unroll
    for (int i = 0; i < 4; i++) {
        int ty = ty0 + i * 8;
        t[ty][tx] = W[(size_t)(k0 + ty) * N + n0 + tx];
    }
    __syncthreads();
#pragma unroll
    for (int i = 0; i < 4; i++) {
        int n = n0 + ty0 + i * 8;
        int k = k0 + tx;
        float x = t[tx][ty0 + i * 8];
        __nv_bfloat16 hi = __float2bfloat16(x);
        __nv_bfloat16 lo = __float2bfloat16(x - __bfloat162float(hi));
        size_t b = (size_t)n * K2 + k;
        Wt[b]           = hi;
        Wt[b + HID]     = hi;
        Wt[b + 2 * HID] = lo;
    }
}

// -------- per-head RMSNorm+RoPE -> bf16 splits; V split only -----------------
__global__ void norm_rope_kernel(const float* __restrict__ cosT,
                                 const float* __restrict__ sinT,
                                 const float* __restrict__ qscale,
                                 const float* __restrict__ kscale)
{
    int s = blockIdx.x;
    int h = blockIdx.y;   // 0..15 Q, 16..19 K, 20..23 V
    int d = threadIdx.x;

    if (h >= NH + NKV) {
        size_t i = (size_t)s * KVW + (h - NH - NKV) * HD + d;
        float x = g_V[i];
        __nv_bfloat16 hi = __float2bfloat16(x);
        g_Vh[i] = hi;
        g_Vl[i] = __float2bfloat16(x - __bfloat162float(hi));
        return;
    }

    const float* base;
    const float* sc;
    size_t oidx;
    if (h < NH) { base = g_Q + (size_t)s * HID + h * HD; sc = qscale;
                  oidx = (size_t)s * HID + h * HD + d; }
    else        { base = g_K + (size_t)s * KVW + (h - NH) * HD; sc = kscale;
                  oidx = (size_t)s * KVW + (h - NH) * HD + d; }

    float x = base[d];
    float v = x * x;
#pragma unroll
    for (int m = 16; m > 0; m >>= 1) v += __shfl_xor_sync(0xffffffffu, v, m);

    __shared__ float ws[4];
    __shared__ float rn[HD];
    if ((d & 31) == 0) ws[d >> 5] = v;
    __syncthreads();
    float tot = ws[0] + ws[1] + ws[2] + ws[3];
    float inv = rsqrtf(tot * (1.0f / HD) + EPSV);

    float r = x * inv * sc[d];
    rn[d] = r;
    __syncthreads();
    float rot = (d < 64) ? -rn[d + 64] : rn[d - 64];
    float c  = cosT[(size_t)s * HD + d];
    float sn = sinT[(size_t)s * HD + d];
    float out = r * c + rot * sn;

    __nv_bfloat16 hi = __float2bfloat16(out);
    __nv_bfloat16 lo = __float2bfloat16(out - __bfloat162float(hi));
    if (h < NH) { g_Qh[oidx] = hi; g_Ql[oidx] = lo; }
    else        { g_Kh[oidx] = hi; g_Kl[oidx] = lo; }
}

// ---------------- causal GQA flash attention, HMMA + splits ------------------
// 256 threads = 8 warps; 128 q-rows per CTA; 64-row K/V tiles double-buffered.
#define AP 136
#define KVBUF (4 * 64 * AP)
#define ATT_SMEM ((2 * 128 * AP + 2 * KVBUF) * 2)

__global__ __launch_bounds__(256) void attn_mma()
{
    extern __shared__ char dynsm[];
    __nv_bfloat16* sm = (__nv_bfloat16*)dynsm;
    __nv_bfloat16* Qh = sm;
    __nv_bfloat16* Ql = sm + 128 * AP;
    __nv_bfloat16* KV = sm + 2 * 128 * AP;

    const int qb = 15 - blockIdx.x;
    const int h  = blockIdx.y;
    const int kv = h >> 2;
    const int tid = threadIdx.x, w = tid >> 5, l = tid & 31;
    const float scl = 0.08838834764831845f;
    const int kmax = 2 * qb + 1;

    const __nv_bfloat16* gkh = g_Kh + kv * HD;
    const __nv_bfloat16* gkl = g_Kl + kv * HD;
    const __nv_bfloat16* gvh = g_Vh + kv * HD;
    const __nv_bfloat16* gvl = g_Vl + kv * HD;

#define ISSUE_KV(kb) do {                                                              \
    __nv_bfloat16* _d = KV + ((kb) & 1) * KVBUF;                                       \
    size_t _g0 = (size_t)((kb) * 64) * KVW;                                            \
    _Pragma("unroll")                                                                  \
    for (int _i = 0; _i < 4; _i++) {                                                   \
        int _id = _i * 256 + tid; int _r = _id >> 4, _u = _id & 15;                    \
        size_t _go = _g0 + (size_t)_r * KVW + _u * 8;                                  \
        int _so = _r * AP + _u * 8;                                                    \
        cpa16(_d + _so,               gkh + _go);                                      \
        cpa16(_d + 64 * AP + _so,     gkl + _go);                                      \
        cpa16(_d + 2 * 64 * AP + _so, gvh + _go);                                      \
        cpa16(_d + 3 * 64 * AP + _so, gvl + _go);                                      \
    }                                                                                  \
    asm volatile("cp.async.commit_group;" ::: "memory");                               \
} while (0)

    ISSUE_KV(0);

    // load Q tiles (128 rows x 128 d)
    {
        const __nv_bfloat16* gh = g_Qh + (size_t)(qb * 128) * HID + h * HD;
        const __nv_bfloat16* gl = g_Ql + (size_t)(qb * 128) * HID + h * HD;
#pragma unroll
        for (int i = 0; i < 8; i++) {
            int id = i * 256 + tid;
            int r = id >> 4, u = id & 15;
            *(uint4*)(Qh + r * AP + u * 8) = *(const uint4*)(gh + (size_t)r * HID + u * 8);
            *(uint4*)(Ql + r * AP + u * 8) = *(const uint4*)(gl + (size_t)r * HID + u * 8);
        }
    }

    const uint32_t qa  = smem_u32(Qh), qla = smem_u32(Ql);
    const uint32_t aOff = (uint32_t)((w * 16 + (l & 15)) * AP + ((l >> 4) << 3)) * 2;

    float m0 = -1e30f, m1 = -1e30f, ls0 = 0.0f, ls1 = 0.0f;
    float accO[16][4];
#pragma unroll
    for (int i = 0; i < 16; i++)
#pragma unroll
        for (int j = 0; j < 4; j++) accO[i][j] = 0.0f;

    for (int kb = 0; kb <= kmax; kb++) {
        asm volatile("cp.async.wait_group 0;" ::: "memory");
        __syncthreads();
        if (kb < kmax) ISSUE_KV(kb + 1);

        const __nv_bfloat16* buf = KV + (kb & 1) * KVBUF;
        const uint32_t kha = smem_u32(buf);
        const uint32_t kla = kha + 64 * AP * 2;
        const uint32_t vha = kha + 2 * 64 * AP * 2;
        const uint32_t vla = kha + 3 * 64 * AP * 2;

        // ---- S = Qh·Kh + Ql·Kh + Qh·Kl ----
        float S[8][4];
#pragma unroll
        for (int t = 0; t < 8; t++)
#pragma unroll
            for (int e = 0; e < 4; e++) S[t][e] = 0.0f;

#pragma unroll
        for (int pass = 0; pass < 3; pass++) {
            const uint32_t Ab = (pass == 1) ? qla : qa;
            const uint32_t Bb = (pass == 2) ? kla : kha;
#pragma unroll
            for (int ks = 0; ks < 8; ks++) {
                uint32_t af[4], bfr[4][4];
                ldsm4(af, Ab + aOff + ks * 32);
#pragma unroll
                for (int g = 0; g < 4; g++)
                    ldsm4(bfr[g], Bb + (uint32_t)((g * 16 + (l & 7) + (((l >> 4) & 1) << 3)) * AP
                                                  + (((l >> 3) & 1) << 3)) * 2 + ks * 32);
#pragma unroll
                for (int t = 0; t < 8; t++)
                    mma16816(S[t], af, &bfr[t >> 1][(t & 1) * 2]);
            }
        }

#pragma unroll
        for (int t = 0; t < 8; t++)
#pragma unroll
            for (int e = 0; e < 4; e++) S[t][e] *= scl;

        if (kb >= 2 * qb) {   // masking needed near/above diagonal
            int r0 = qb * 128 + w * 16 + (l >> 2), r1 = r0 + 8;
            int cbase = kb * 64 + (l & 3) * 2;
#pragma unroll
            for (int t = 0; t < 8; t++) {
                int cb = cbase + t * 8;
                if (cb     > r0) S[t][0] = -1e30f;
                if (cb + 1 > r0) S[t][1] = -1e30f;
                if (cb     > r1) S[t][2] = -1e30f;
                if (cb + 1 > r1) S[t][3] = -1e30f;
            }
        }

        float mx0 = -1e30f, mx1 = -1e30f;
#pragma unroll
        for (int t = 0; t < 8; t++) {
            mx0 = fmaxf(mx0, fmaxf(S[t][0], S[t][1]));
            mx1 = fmaxf(mx1, fmaxf(S[t][2], S[t][3]));
        }
        mx0 = fmaxf(mx0, __shfl_xor_sync(0xffffffffu, mx0, 1));
        mx0 = fmaxf(mx0, __shfl_xor_sync(0xffffffffu, mx0, 2));
        mx1 = fmaxf(mx1, __shfl_xor_sync(0xffffffffu, mx1, 1));
        mx1 = fmaxf(mx1, __shfl_xor_sync(0xffffffffu, mx1, 2));

        float nm0 = fmaxf(m0, mx0), nm1 = fmaxf(m1, mx1);
        float cr0 = __expf(m0 - nm0), cr1 = __expf(m1 - nm1);
        m0 = nm0; m1 = nm1;
        ls0 *= cr0; ls1 *= cr1;
#pragma unroll
        for (int t = 0; t < 16; t++) {
            accO[t][0] *= cr0; accO[t][1] *= cr0;
            accO[t][2] *= cr1; accO[t][3] *= cr1;
        }

        uint32_t Pha[4][4], Pla[4][4];
        float rs0 = 0.0f, rs1 = 0.0f;
#pragma unroll
        for (int t = 0; t < 8; t++) {
            float p0 = __expf(S[t][0] - nm0), p1 = __expf(S[t][1] - nm0);
            float p2 = __expf(S[t][2] - nm1), p3 = __expf(S[t][3] - nm1);
            rs0 += p0 + p1; rs1 += p2 + p3;
            __nv_bfloat16 b0 = __float2bfloat16(p0), b1 = __float2bfloat16(p1);
            __nv_bfloat16 b2 = __float2bfloat16(p2), b3 = __float2bfloat16(p3);
            uint32_t ph01 = packbf(__bfloat162float(b0), __bfloat162float(b1));
            uint32_t ph23 = packbf(__bfloat162float(b2), __bfloat162float(b3));
            uint32_t pl01 = packbf(p0 - __bfloat162float(b0), p1 - __bfloat162float(b1));
            uint32_t pl23 = packbf(p2 - __bfloat162float(b2), p3 - __bfloat162float(b3));
            int kc = t >> 1, hi = (t & 1) * 2;
            Pha[kc][hi]     = ph01;
            Pha[kc][hi + 1] = ph23;
            Pla[kc][hi]     = pl01;
            Pla[kc][hi + 1] = pl23;
        }
        rs0 += __shfl_xor_sync(0xffffffffu, rs0, 1);
        rs0 += __shfl_xor_sync(0xffffffffu, rs0, 2);
        rs1 += __shfl_xor_sync(0xffffffffu, rs1, 1);
        rs1 += __shfl_xor_sync(0xffffffffu, rs1, 2);
        ls0 += rs0; ls1 += rs1;

        // ---- PV: acc += Ph·Vh + Pl·Vh + Ph·Vl ----
#pragma unroll
        for (int kc = 0; kc < 4; kc++) {
            uint32_t vb[8][4];
#pragma unroll
            for (int g = 0; g < 8; g++)
                ldsm4t(vb[g], vha + (uint32_t)((kc * 16 + (l & 15)) * AP
                                               + (g * 16 + ((l >> 4) << 3))) * 2);
#pragma unroll
            for (int nd = 0; nd < 16; nd++)
                mma16816(accO[nd], Pha[kc], &vb[nd >> 1][(nd & 1) * 2]);
#pragma unroll
            for (int nd = 0; nd < 16; nd++)
                mma16816(accO[nd], Pla[kc], &vb[nd >> 1][(nd & 1) * 2]);
#pragma unroll
            for (int g = 0; g < 8; g++)
                ldsm4t(vb[g], vla + (uint32_t)((kc * 16 + (l & 15)) * AP
                                               + (g * 16 + ((l >> 4) << 3))) * 2);
#pragma unroll
            for (int nd = 0; nd < 16; nd++)
                mma16816(accO[nd], Pha[kc], &vb[nd >> 1][(nd & 1) * 2]);
        }
    }
#undef ISSUE_KV

    // epilogue: write AO2 splits directly ([hi | lo | hi])
    float inv0 = 1.0f / ls0, inv1 = 1.0f / ls1;
    int r0 = qb * 128 + w * 16 + (l >> 2);
    int cc = h * HD + (l & 3) * 2;
#pragma unroll
    for (int nd = 0; nd < 16; nd++) {
        float v00 = accO[nd][0] * inv0, v01 = accO[nd][1] * inv0;
        float v10 = accO[nd][2] * inv1, v11 = accO[nd][3] * inv1;
        __nv_bfloat162 h0 = __floats2bfloat162_rn(v00, v01);
        __nv_bfloat162 l0v = __floats2bfloat162_rn(v00 - __bfloat162float(h0.x),
                                                   v01 - __bfloat162float(h0.y));
        __nv_bfloat162 h1 = __floats2bfloat162_rn(v10, v11);
        __nv_bfloat162 l1v = __floats2bfloat162_rn(v10 - __bfloat162float(h1.x),
                                                   v11 - __bfloat162float(h1.y));
        size_t b0 = (size_t)r0 * K2 + cc + nd * 8;
        size_t b1 = (size_t)(r0 + 8) * K2 + cc + nd * 8;
        *(__nv_bfloat162*)(g_AO2 + b0)            = h0;
        *(__nv_bfloat162*)(g_AO2 + b0 + HID)      = l0v;
        *(__nv_bfloat162*)(g_AO2 + b0 + 2 * HID)  = h0;
        *(__nv_bfloat162*)(g_AO2 + b1)            = h1;
        *(__nv_bfloat162*)(g_AO2 + b1 + HID)      = l1v;
        *(__nv_bfloat162*)(g_AO2 + b1 + 2 * HID)  = h1;
    }
}

// ---------------- final RMSNorm ----------------------------------------------
__global__ void final_norm_kernel(const float* __restrict__ sc, float* __restrict__ out)
{
    int s = blockIdx.x;
    const float* y = g_Y + (size_t)s * HID;
    float v = 0.0f;
    for (int d = threadIdx.x; d < HID; d += 256) { float x = y[d]; v += x * x; }
#pragma unroll
    for (int m = 16; m > 0; m >>= 1) v += __shfl_xor_sync(0xffffffffu, v, m);
    __shared__ float ws[8];
    if ((threadIdx.x & 31) == 0) ws[threadIdx.x >> 5] = v;
    __syncthreads();
    float tot = 0.0f;
#pragma unroll
    for (int i = 0; i < 8; i++) tot += ws[i];
    float inv = rsqrtf(tot * (1.0f / HID) + EPSV);
    for (int d = threadIdx.x; d < HID; d += 256)
        out[(size_t)s * HID + d] = y[d] * inv * sc[d];
}

// ---------------- launch -----------------------------------------------------
#define GEMM_SMEM (NSTG * 2 * 128 * GP * 2)

extern "C" void kernel_launch(void* const* d_in, const int* in_sizes, int n_in,
                              void* d_out, int out_size)
{
    const float* hidden = (const float*)d_in[0];
    const float* cosT   = (const float*)d_in[1];
    const float* sinT   = (const float*)d_in[2];
    const float* Wq     = (const float*)d_in[3];
    const float* Wk     = (const float*)d_in[4];
    const float* Wv     = (const float*)d_in[5];
    const float* Wo     = (const float*)d_in[6];
    const float* qs     = (const float*)d_in[7];
    const float* ks     = (const float*)d_in[8];
    const float* ls     = (const float*)d_in[9];
    float* out = (float*)d_out;

    __nv_bfloat16 *A2p, *Wqkv2p, *Wo2p;
    cudaGetSymbolAddress((void**)&A2p,    g_A2);
    cudaGetSymbolAddress((void**)&Wqkv2p, g_Wqkv2);
    cudaGetSymbolAddress((void**)&Wo2p,   g_Wo2);

    cudaFuncSetAttribute(gemm_qkv, cudaFuncAttributeMaxDynamicSharedMemorySize, GEMM_SMEM);
    cudaFuncSetAttribute(gemm_wo,  cudaFuncAttributeMaxDynamicSharedMemorySize, GEMM_SMEM);
    cudaFuncSetAttribute(attn_mma, cudaFuncAttributeMaxDynamicSharedMemorySize, ATT_SMEM);

    // split-convert activations + weights (weights packed into one QKV buffer)
    conv_act<<<SEQ * HID / 512, 256>>>(hidden, A2p);
    conv_wt<<<dim3(HID / 32, HID / 32), dim3(32, 8)>>>(Wq, Wqkv2p, HID);
    conv_wt<<<dim3(KVW / 32, HID / 32), dim3(32, 8)>>>(Wk, Wqkv2p + (size_t)HID * K2, KVW);
    conv_wt<<<dim3(KVW / 32, HID / 32), dim3(32, 8)>>>(Wv, Wqkv2p + (size_t)(HID + KVW) * K2, KVW);
    conv_wt<<<dim3(HID / 32, HID / 32), dim3(32, 8)>>>(Wo, Wo2p, HID);

    // fused QKV projection
    gemm_qkv<<<dim3(NQKV / 128, SEQ / 128), 256, GEMM_SMEM>>>();

    // per-head RMSNorm + RoPE + splits
    norm_rope_kernel<<<dim3(SEQ, NH + 2 * NKV), HD>>>(cosT, sinT, qs, ks);

    // causal GQA attention (writes AO2 splits directly)
    attn_mma<<<dim3(SEQ / 128, NH), 256, ATT_SMEM>>>();

    // output projection
    gemm_wo<<<dim3(HID / 128, SEQ / 128), 256, GEMM_SMEM>>>();

    // final RMSNorm -> d_out
    final_norm_kernel<<<SEQ, 256>>>(ls, out);
}

// round 6
// speedup vs baseline: 4.1322x; 1.3791x over previous
#include <cuda_runtime.h>
#include <cuda_bf16.h>
#include <cuda_fp16.h>
#include <cstdint>
#include <math.h>

#define SEQ 2048
#define HID 2048
#define HD  128
#define NH  16
#define NKV 4
#define KVW (NKV*HD)           // 512
#define NQKV (HID + 2*KVW)     // 3072
#define EPSV 1e-6f
#define BKG 64
#define NSTG 4
#define KCH (HID / BKG)        // 32 k-chunks
#define GP  72                 // gemm smem row stride (halves)

// ---------------- scratch ----------------------------------------------------
__device__ float g_Q[SEQ * HID];
__device__ float g_K[SEQ * KVW];
__device__ float g_V[SEQ * KVW];
__device__ float g_Y[SEQ * HID];

__device__ __half g_Ah[SEQ * HID];               // hidden split hi (fp16)
__device__ __half g_Al[SEQ * HID];               // hidden split lo
__device__ __half g_AOh[SEQ * HID];              // attention-out split hi
__device__ __half g_AOl[SEQ * HID];
__device__ __half g_Wqkv[NQKV * HID];            // W^T fp16 (hi only)
__device__ __half g_Wo[HID * HID];

__device__ __nv_bfloat16 g_Qh[SEQ * HID];
__device__ __nv_bfloat16 g_Ql[SEQ * HID];
__device__ __nv_bfloat16 g_Kh[SEQ * KVW];
__device__ __nv_bfloat16 g_Kl[SEQ * KVW];
__device__ __nv_bfloat16 g_Vh[SEQ * KVW];
__device__ __nv_bfloat16 g_Vl[SEQ * KVW];

// ======================= helpers =============================================
__device__ __forceinline__ uint32_t smem_u32(const void* p) {
    uint32_t a;
    asm("{ .reg .u64 t; cvta.to.shared.u64 t, %1; cvt.u32.u64 %0, t; }" : "=r"(a) : "l"(p));
    return a;
}
__device__ __forceinline__ void ldsm4(uint32_t* r, uint32_t addr) {
    asm volatile("ldmatrix.sync.aligned.m8n8.x4.shared.b16 {%0,%1,%2,%3}, [%4];"
        : "=r"(r[0]), "=r"(r[1]), "=r"(r[2]), "=r"(r[3]) : "r"(addr));
}
__device__ __forceinline__ void ldsm4t(uint32_t* r, uint32_t addr) {
    asm volatile("ldmatrix.sync.aligned.m8n8.x4.trans.shared.b16 {%0,%1,%2,%3}, [%4];"
        : "=r"(r[0]), "=r"(r[1]), "=r"(r[2]), "=r"(r[3]) : "r"(addr));
}
__device__ __forceinline__ void mma_bf16(float* c, const uint32_t* a, const uint32_t* b) {
    asm volatile(
        "mma.sync.aligned.m16n8k16.row.col.f32.bf16.bf16.f32 "
        "{%0,%1,%2,%3}, {%4,%5,%6,%7}, {%8,%9}, {%0,%1,%2,%3};"
        : "+f"(c[0]), "+f"(c[1]), "+f"(c[2]), "+f"(c[3])
        : "r"(a[0]), "r"(a[1]), "r"(a[2]), "r"(a[3]), "r"(b[0]), "r"(b[1]));
}
__device__ __forceinline__ void mma_f16(float* c, const uint32_t* a, const uint32_t* b) {
    asm volatile(
        "mma.sync.aligned.m16n8k16.row.col.f32.f16.f16.f32 "
        "{%0,%1,%2,%3}, {%4,%5,%6,%7}, {%8,%9}, {%0,%1,%2,%3};"
        : "+f"(c[0]), "+f"(c[1]), "+f"(c[2]), "+f"(c[3])
        : "r"(a[0]), "r"(a[1]), "r"(a[2]), "r"(a[3]), "r"(b[0]), "r"(b[1]));
}
__device__ __forceinline__ void cpa16(void* s, const void* g) {
    uint32_t sa = smem_u32(s);
    asm volatile("cp.async.cg.shared.global [%0], [%1], 16;" :: "r"(sa), "l"(g));
}
__device__ __forceinline__ uint32_t packbf(float a, float b) {
    __nv_bfloat162 t = __floats2bfloat162_rn(a, b);
    return *(uint32_t*)&t;
}

// ===== fp16 2-term GEMM core: C = (Ah+Al) @ B^T, 4-stage cp.async ===========
// smem per stage: [Ah 128xGP | Al 128xGP | B 128xGP] halves.
#define STAGE_HALF (3 * 128 * GP)
#define GEMM_SMEM  (NSTG * STAGE_HALF * 2)

struct GemmAcc { float a[4][4][4]; };

__device__ __forceinline__ void gemm_core(const __half* __restrict__ Ah,
                                          const __half* __restrict__ Al,
                                          const __half* __restrict__ B,
                                          int bm, int bn, __half* gs, GemmAcc& G)
{
    const int tid  = threadIdx.x;
    const int wid  = tid >> 5, lane = tid & 31;
    const int wm   = wid & 1, wn = wid >> 1;
    const uint32_t sbase = smem_u32(gs);

#define ISSUE(c) do {                                                                   \
    int _k0 = (c) * BKG;                                                                \
    __half* _sA = gs + ((c) % NSTG) * STAGE_HALF;                                       \
    __half* _sL = _sA + 128 * GP;                                                       \
    __half* _sB = _sL + 128 * GP;                                                       \
    _Pragma("unroll")                                                                   \
    for (int _i = 0; _i < 4; _i++) {                                                    \
        int _id = _i * 256 + tid; int _r = _id >> 3, _u = _id & 7;                      \
        int _so = _r * GP + _u * 8;                                                     \
        size_t _ga = (size_t)(bm + _r) * HID + _k0 + _u * 8;                            \
        cpa16(_sA + _so, Ah + _ga);                                                     \
        cpa16(_sL + _so, Al + _ga);                                                     \
        cpa16(_sB + _so, B + (size_t)(bn + _r) * HID + _k0 + _u * 8);                   \
    }                                                                                   \
    asm volatile("cp.async.commit_group;" ::: "memory");                                \
} while (0)

#pragma unroll
    for (int i = 0; i < 4; i++)
#pragma unroll
        for (int j = 0; j < 4; j++)
#pragma unroll
            for (int k = 0; k < 4; k++) G.a[i][j][k] = 0.0f;

    ISSUE(0); ISSUE(1); ISSUE(2);

    const uint32_t aOff = (uint32_t)((wm * 64 + (lane & 15)) * GP + ((lane >> 4) << 3)) * 2;
    const uint32_t bOff = (uint32_t)((wn * 32 + (lane & 7) + (((lane >> 4) & 1) << 3)) * GP
                                     + (((lane >> 3) & 1) << 3)) * 2;

    for (int c = 0; c < KCH; c++) {
        asm volatile("cp.async.wait_group 2;" ::: "memory");
        __syncthreads();
        if (c + 3 < KCH) { ISSUE(c + 3); }
        else { asm volatile("cp.async.commit_group;" ::: "memory"); }

        const uint32_t aB = sbase + (c % NSTG) * (STAGE_HALF * 2);
        const uint32_t lB = aB + 128 * GP * 2;
        const uint32_t bB = lB + 128 * GP * 2;
#pragma unroll
        for (int ks = 0; ks < 4; ks++) {
            uint32_t ah[4][4], al[4][4], bfr[2][4];
#pragma unroll
            for (int mi = 0; mi < 4; mi++) {
                ldsm4(ah[mi], aB + aOff + mi * (16 * GP * 2) + ks * 32);
                ldsm4(al[mi], lB + aOff + mi * (16 * GP * 2) + ks * 32);
            }
#pragma unroll
            for (int nj = 0; nj < 2; nj++)
                ldsm4(bfr[nj], bB + bOff + nj * (16 * GP * 2) + ks * 32);
#pragma unroll
            for (int mi = 0; mi < 4; mi++)
#pragma unroll
                for (int ni = 0; ni < 4; ni++) {
                    mma_f16(G.a[mi][ni], ah[mi], &bfr[ni >> 1][(ni & 1) * 2]);
                    mma_f16(G.a[mi][ni], al[mi], &bfr[ni >> 1][(ni & 1) * 2]);
                }
        }
    }
#undef ISSUE
}

// ---- fused QKV projection ----
__global__ __launch_bounds__(256) void gemm_qkv()
{
    extern __shared__ char dynsm[];
    GemmAcc G;
    const int bm = blockIdx.y * 128, bn = blockIdx.x * 128;
    gemm_core(g_Ah, g_Al, g_Wqkv, bm, bn, (__half*)dynsm, G);

    float* Cb; int Nw, c0;
    if (bn < HID)            { Cb = g_Q; Nw = HID; c0 = bn; }
    else if (bn < HID + KVW) { Cb = g_K; Nw = KVW; c0 = bn - HID; }
    else                     { Cb = g_V; Nw = KVW; c0 = bn - HID - KVW; }

    const int lane = threadIdx.x & 31, wid = threadIdx.x >> 5;
    const int cr = bm + (wid & 1) * 64 + (lane >> 2);
    const int cc = c0 + (wid >> 1) * 32 + (lane & 3) * 2;
#pragma unroll
    for (int mi = 0; mi < 4; mi++)
#pragma unroll
        for (int ni = 0; ni < 4; ni++) {
            *(float2*)&Cb[(size_t)(cr + mi * 16) * Nw + cc + ni * 8] =
                make_float2(G.a[mi][ni][0], G.a[mi][ni][1]);
            *(float2*)&Cb[(size_t)(cr + mi * 16 + 8) * Nw + cc + ni * 8] =
                make_float2(G.a[mi][ni][2], G.a[mi][ni][3]);
        }
}

// ---- Wo projection ----
__global__ __launch_bounds__(256) void gemm_wo()
{
    extern __shared__ char dynsm[];
    GemmAcc G;
    const int bm = blockIdx.y * 128, bn = blockIdx.x * 128;
    gemm_core(g_AOh, g_AOl, g_Wo, bm, bn, (__half*)dynsm, G);

    const int lane = threadIdx.x & 31, wid = threadIdx.x >> 5;
    const int cr = bm + (wid & 1) * 64 + (lane >> 2);
    const int cc = bn + (wid >> 1) * 32 + (lane & 3) * 2;
#pragma unroll
    for (int mi = 0; mi < 4; mi++)
#pragma unroll
        for (int ni = 0; ni < 4; ni++) {
            *(float2*)&g_Y[(size_t)(cr + mi * 16) * HID + cc + ni * 8] =
                make_float2(G.a[mi][ni][0], G.a[mi][ni][1]);
            *(float2*)&g_Y[(size_t)(cr + mi * 16 + 8) * HID + cc + ni * 8] =
                make_float2(G.a[mi][ni][2], G.a[mi][ni][3]);
        }
}

// =========== split-convert hidden: f32 -> Ah, Al fp16 ========================
__global__ void conv_act(const float* __restrict__ X)
{
    int idx = (blockIdx.x * blockDim.x + threadIdx.x) * 2;
    float2 x = *(const float2*)(X + idx);
    __half h0 = __float2half_rn(x.x);
    __half h1 = __float2half_rn(x.y);
    __half l0 = __float2half_rn(x.x - __half2float(h0));
    __half l1 = __float2half_rn(x.y - __half2float(h1));
    __half2 hv; hv.x = h0; hv.y = h1;
    __half2 lv; lv.x = l0; lv.y = l1;
    *(__half2*)(g_Ah + idx) = hv;
    *(__half2*)(g_Al + idx) = lv;
}

// ==== transpose: W[HID,N] f32 -> Wt[N,HID] fp16 (hi only) ====================
__global__ void conv_wt(const float* __restrict__ W, __half* __restrict__ Wt, int N)
{
    __shared__ float t[32][33];
    int n0 = blockIdx.x * 32, k0 = blockIdx.y * 32;
    int tx = threadIdx.x, ty0 = threadIdx.y;
#pragma unroll
    for (int i = 0; i < 4; i++) {
        int ty = ty0 + i * 8;
        t[ty][tx] = W[(size_t)(k0 + ty) * N + n0 + tx];
    }
    __syncthreads();
#pragma unroll
    for (int i = 0; i < 4; i++) {
        int n = n0 + ty0 + i * 8;
        int k = k0 + tx;
        Wt[(size_t)n * HID + k] = __float2half_rn(t[tx][ty0 + i * 8]);
    }
}

// -------- per-head RMSNorm+RoPE -> bf16 splits; V split only -----------------
__global__ void norm_rope_kernel(const float* __restrict__ cosT,
                                 const float* __restrict__ sinT,
                                 const float* __restrict__ qscale,
                                 const float* __restrict__ kscale)
{
    int s = blockIdx.x;
    int h = blockIdx.y;   // 0..15 Q, 16..19 K, 20..23 V
    int d = threadIdx.x;

    if (h >= NH + NKV) {
        size_t i = (size_t)s * KVW + (h - NH - NKV) * HD + d;
        float x = g_V[i];
        __nv_bfloat16 hi = __float2bfloat16(x);
        g_Vh[i] = hi;
        g_Vl[i] = __float2bfloat16(x - __bfloat162float(hi));
        return;
    }

    const float* base;
    const float* sc;
    size_t oidx;
    if (h < NH) { base = g_Q + (size_t)s * HID + h * HD; sc = qscale;
                  oidx = (size_t)s * HID + h * HD + d; }
    else        { base = g_K + (size_t)s * KVW + (h - NH) * HD; sc = kscale;
                  oidx = (size_t)s * KVW + (h - NH) * HD + d; }

    float x = base[d];
    float v = x * x;
#pragma unroll
    for (int m = 16; m > 0; m >>= 1) v += __shfl_xor_sync(0xffffffffu, v, m);

    __shared__ float ws[4];
    __shared__ float rn[HD];
    if ((d & 31) == 0) ws[d >> 5] = v;
    __syncthreads();
    float tot = ws[0] + ws[1] + ws[2] + ws[3];
    float inv = rsqrtf(tot * (1.0f / HD) + EPSV);

    float r = x * inv * sc[d];
    rn[d] = r;
    __syncthreads();
    float rot = (d < 64) ? -rn[d + 64] : rn[d - 64];
    float c  = cosT[(size_t)s * HD + d];
    float sn = sinT[(size_t)s * HD + d];
    float out = r * c + rot * sn;

    __nv_bfloat16 hi = __float2bfloat16(out);
    __nv_bfloat16 lo = __float2bfloat16(out - __bfloat162float(hi));
    if (h < NH) { g_Qh[oidx] = hi; g_Ql[oidx] = lo; }
    else        { g_Kh[oidx] = hi; g_Kl[oidx] = lo; }
}

// ---------------- causal GQA flash attention, bf16 3-term HMMA ---------------
#define AP 136
#define KVBUF (4 * 64 * AP)
#define ATT_SMEM ((2 * 128 * AP + 2 * KVBUF) * 2)

__global__ __launch_bounds__(256) void attn_mma()
{
    extern __shared__ char dynsm[];
    __nv_bfloat16* sm = (__nv_bfloat16*)dynsm;
    __nv_bfloat16* Qh = sm;
    __nv_bfloat16* Ql = sm + 128 * AP;
    __nv_bfloat16* KV = sm + 2 * 128 * AP;

    const int qb = 15 - blockIdx.x;
    const int h  = blockIdx.y;
    const int kv = h >> 2;
    const int tid = threadIdx.x, w = tid >> 5, l = tid & 31;
    const float scl = 0.08838834764831845f;
    const int kmax = 2 * qb + 1;

    const __nv_bfloat16* gkh = g_Kh + kv * HD;
    const __nv_bfloat16* gkl = g_Kl + kv * HD;
    const __nv_bfloat16* gvh = g_Vh + kv * HD;
    const __nv_bfloat16* gvl = g_Vl + kv * HD;

#define ISSUE_KV(kb) do {                                                              \
    __nv_bfloat16* _d = KV + ((kb) & 1) * KVBUF;                                       \
    size_t _g0 = (size_t)((kb) * 64) * KVW;                                            \
    _Pragma("unroll")                                                                  \
    for (int _i = 0; _i < 4; _i++) {                                                   \
        int _id = _i * 256 + tid; int _r = _id >> 4, _u = _id & 15;                    \
        size_t _go = _g0 + (size_t)_r * KVW + _u * 8;                                  \
        int _so = _r * AP + _u * 8;                                                    \
        cpa16(_d + _so,               gkh + _go);                                      \
        cpa16(_d + 64 * AP + _so,     gkl + _go);                                      \
        cpa16(_d + 2 * 64 * AP + _so, gvh + _go);                                      \
        cpa16(_d + 3 * 64 * AP + _so, gvl + _go);                                      \
    }                                                                                  \
    asm volatile("cp.async.commit_group;" ::: "memory");                               \
} while (0)

    ISSUE_KV(0);

    {
        const __nv_bfloat16* gh = g_Qh + (size_t)(qb * 128) * HID + h * HD;
        const __nv_bfloat16* gl = g_Ql + (size_t)(qb * 128) * HID + h * HD;
#pragma unroll
        for (int i = 0; i < 8; i++) {
            int id = i * 256 + tid;
            int r = id >> 4, u = id & 15;
            *(uint4*)(Qh + r * AP + u * 8) = *(const uint4*)(gh + (size_t)r * HID + u * 8);
            *(uint4*)(Ql + r * AP + u * 8) = *(const uint4*)(gl + (size_t)r * HID + u * 8);
        }
    }

    const uint32_t qa  = smem_u32(Qh), qla = smem_u32(Ql);
    const uint32_t aOff = (uint32_t)((w * 16 + (l & 15)) * AP + ((l >> 4) << 3)) * 2;

    float m0 = -1e30f, m1 = -1e30f, ls0 = 0.0f, ls1 = 0.0f;
    float accO[16][4];
#pragma unroll
    for (int i = 0; i < 16; i++)
#pragma unroll
        for (int j = 0; j < 4; j++) accO[i][j] = 0.0f;

    for (int kb = 0; kb <= kmax; kb++) {
        asm volatile("cp.async.wait_group 0;" ::: "memory");
        __syncthreads();
        if (kb < kmax) ISSUE_KV(kb + 1);

        const __nv_bfloat16* buf = KV + (kb & 1) * KVBUF;
        const uint32_t kha = smem_u32(buf);
        const uint32_t kla = kha + 64 * AP * 2;
        const uint32_t vha = kha + 2 * 64 * AP * 2;
        const uint32_t vla = kha + 3 * 64 * AP * 2;

        // ---- S = Qh·Kh + Ql·Kh + Qh·Kl  (fragment-reuse order) ----
        float S[8][4];
#pragma unroll
        for (int t = 0; t < 8; t++)
#pragma unroll
            for (int e = 0; e < 4; e++) S[t][e] = 0.0f;

#pragma unroll
        for (int ks = 0; ks < 8; ks++) {
            uint32_t afh[4], afl[4], bf2[4][4];
            ldsm4(afh, qa  + aOff + ks * 32);
            ldsm4(afl, qla + aOff + ks * 32);
#pragma unroll
            for (int g = 0; g < 4; g++)
                ldsm4(bf2[g], kha + (uint32_t)((g * 16 + (l & 7) + (((l >> 4) & 1) << 3)) * AP
                                               + (((l >> 3) & 1) << 3)) * 2 + ks * 32);
#pragma unroll
            for (int t = 0; t < 8; t++)
                mma_bf16(S[t], afh, &bf2[t >> 1][(t & 1) * 2]);
#pragma unroll
            for (int t = 0; t < 8; t++)
                mma_bf16(S[t], afl, &bf2[t >> 1][(t & 1) * 2]);
#pragma unroll
            for (int g = 0; g < 4; g++)
                ldsm4(bf2[g], kla + (uint32_t)((g * 16 + (l & 7) + (((l >> 4) & 1) << 3)) * AP
                                               + (((l >> 3) & 1) << 3)) * 2 + ks * 32);
#pragma unroll
            for (int t = 0; t < 8; t++)
                mma_bf16(S[t], afh, &bf2[t >> 1][(t & 1) * 2]);
        }

#pragma unroll
        for (int t = 0; t < 8; t++)
#pragma unroll
            for (int e = 0; e < 4; e++) S[t][e] *= scl;

        if (kb >= 2 * qb) {
            int r0 = qb * 128 + w * 16 + (l >> 2), r1 = r0 + 8;
            int cbase = kb * 64 + (l & 3) * 2;
#pragma unroll
            for (int t = 0; t < 8; t++) {
                int cb = cbase + t * 8;
                if (cb     > r0) S[t][0] = -1e30f;
                if (cb + 1 > r0) S[t][1] = -1e30f;
                if (cb     > r1) S[t][2] = -1e30f;
                if (cb + 1 > r1) S[t][3] = -1e30f;
            }
        }

        float mx0 = -1e30f, mx1 = -1e30f;
#pragma unroll
        for (int t = 0; t < 8; t++) {
            mx0 = fmaxf(mx0, fmaxf(S[t][0], S[t][1]));
            mx1 = fmaxf(mx1, fmaxf(S[t][2], S[t][3]));
        }
        mx0 = fmaxf(mx0, __shfl_xor_sync(0xffffffffu, mx0, 1));
        mx0 = fmaxf(mx0, __shfl_xor_sync(0xffffffffu, mx0, 2));
        mx1 = fmaxf(mx1, __shfl_xor_sync(0xffffffffu, mx1, 1));
        mx1 = fmaxf(mx1, __shfl_xor_sync(0xffffffffu, mx1, 2));

        float nm0 = fmaxf(m0, mx0), nm1 = fmaxf(m1, mx1);
        float cr0 = __expf(m0 - nm0), cr1 = __expf(m1 - nm1);
        m0 = nm0; m1 = nm1;
        ls0 *= cr0; ls1 *= cr1;
#pragma unroll
        for (int t = 0; t < 16; t++) {
            accO[t][0] *= cr0; accO[t][1] *= cr0;
            accO[t][2] *= cr1; accO[t][3] *= cr1;
        }

        uint32_t Pha[4][4], Pla[4][4];
        float rs0 = 0.0f, rs1 = 0.0f;
#pragma unroll
        for (int t = 0; t < 8; t++) {
            float p0 = __expf(S[t][0] - nm0), p1 = __expf(S[t][1] - nm0);
            float p2 = __expf(S[t][2] - nm1), p3 = __expf(S[t][3] - nm1);
            rs0 += p0 + p1; rs1 += p2 + p3;
            __nv_bfloat16 b0 = __float2bfloat16(p0), b1 = __float2bfloat16(p1);
            __nv_bfloat16 b2 = __float2bfloat16(p2), b3 = __float2bfloat16(p3);
            uint32_t ph01 = packbf(__bfloat162float(b0), __bfloat162float(b1));
            uint32_t ph23 = packbf(__bfloat162float(b2), __bfloat162float(b3));
            uint32_t pl01 = packbf(p0 - __bfloat162float(b0), p1 - __bfloat162float(b1));
            uint32_t pl23 = packbf(p2 - __bfloat162float(b2), p3 - __bfloat162float(b3));
            int kc = t >> 1, hi = (t & 1) * 2;
            Pha[kc][hi]     = ph01;
            Pha[kc][hi + 1] = ph23;
            Pla[kc][hi]     = pl01;
            Pla[kc][hi + 1] = pl23;
        }
        rs0 += __shfl_xor_sync(0xffffffffu, rs0, 1);
        rs0 += __shfl_xor_sync(0xffffffffu, rs0, 2);
        rs1 += __shfl_xor_sync(0xffffffffu, rs1, 1);
        rs1 += __shfl_xor_sync(0xffffffffu, rs1, 2);
        ls0 += rs0; ls1 += rs1;

        // ---- PV: acc += Ph·Vh + Pl·Vh + Ph·Vl ----
#pragma unroll
        for (int kc = 0; kc < 4; kc++) {
            uint32_t vb[8][4];
#pragma unroll
            for (int g = 0; g < 8; g++)
                ldsm4t(vb[g], vha + (uint32_t)((kc * 16 + (l & 15)) * AP
                                               + (g * 16 + ((l >> 4) << 3))) * 2);
#pragma unroll
            for (int nd = 0; nd < 16; nd++)
                mma_bf16(accO[nd], Pha[kc], &vb[nd >> 1][(nd & 1) * 2]);
#pragma unroll
            for (int nd = 0; nd < 16; nd++)
                mma_bf16(accO[nd], Pla[kc], &vb[nd >> 1][(nd & 1) * 2]);
#pragma unroll
            for (int g = 0; g < 8; g++)
                ldsm4t(vb[g], vla + (uint32_t)((kc * 16 + (l & 15)) * AP
                                               + (g * 16 + ((l >> 4) << 3))) * 2);
#pragma unroll
            for (int nd = 0; nd < 16; nd++)
                mma_bf16(accO[nd], Pha[kc], &vb[nd >> 1][(nd & 1) * 2]);
        }
    }
#undef ISSUE_KV

    // epilogue: write AOh / AOl fp16 splits directly
    float inv0 = 1.0f / ls0, inv1 = 1.0f / ls1;
    int r0 = qb * 128 + w * 16 + (l >> 2);
    int cc = h * HD + (l & 3) * 2;
#pragma unroll
    for (int nd = 0; nd < 16; nd++) {
        float v00 = accO[nd][0] * inv0, v01 = accO[nd][1] * inv0;
        float v10 = accO[nd][2] * inv1, v11 = accO[nd][3] * inv1;
        __half2 h0 = __floats2half2_rn(v00, v01);
        __half2 l0v = __floats2half2_rn(v00 - __half2float(h0.x), v01 - __half2float(h0.y));
        __half2 h1 = __floats2half2_rn(v10, v11);
        __half2 l1v = __floats2half2_rn(v10 - __half2float(h1.x), v11 - __half2float(h1.y));
        size_t b0 = (size_t)r0 * HID + cc + nd * 8;
        size_t b1 = (size_t)(r0 + 8) * HID + cc + nd * 8;
        *(__half2*)(g_AOh + b0) = h0;
        *(__half2*)(g_AOl + b0) = l0v;
        *(__half2*)(g_AOh + b1) = h1;
        *(__half2*)(g_AOl + b1) = l1v;
    }
}

// ---------------- final RMSNorm ----------------------------------------------
__global__ void final_norm_kernel(const float* __restrict__ sc, float* __restrict__ out)
{
    int s = blockIdx.x;
    const float* y = g_Y + (size_t)s * HID;
    float v = 0.0f;
    for (int d = threadIdx.x; d < HID; d += 256) { float x = y[d]; v += x * x; }
#pragma unroll
    for (int m = 16; m > 0; m >>= 1) v += __shfl_xor_sync(0xffffffffu, v, m);
    __shared__ float ws[8];
    if ((threadIdx.x & 31) == 0) ws[threadIdx.x >> 5] = v;
    __syncthreads();
    float tot = 0.0f;
#pragma unroll
    for (int i = 0; i < 8; i++) tot += ws[i];
    float inv = rsqrtf(tot * (1.0f / HID) + EPSV);
    for (int d = threadIdx.x; d < HID; d += 256)
        out[(size_t)s * HID + d] = y[d] * inv * sc[d];
}

// ---------------- launch -----------------------------------------------------
extern "C" void kernel_launch(void* const* d_in, const int* in_sizes, int n_in,
                              void* d_out, int out_size)
{
    const float* hidden = (const float*)d_in[0];
    const float* cosT   = (const float*)d_in[1];
    const float* sinT   = (const float*)d_in[2];
    const float* Wq     = (const float*)d_in[3];
    const float* Wk     = (const float*)d_in[4];
    const float* Wv     = (const float*)d_in[5];
    const float* Wo     = (const float*)d_in[6];
    const float* qs     = (const float*)d_in[7];
    const float* ks     = (const float*)d_in[8];
    const float* ls     = (const float*)d_in[9];
    float* out = (float*)d_out;

    __half *Wqkvp, *Wop;
    cudaGetSymbolAddress((void**)&Wqkvp, g_Wqkv);
    cudaGetSymbolAddress((void**)&Wop,   g_Wo);

    cudaFuncSetAttribute(gemm_qkv, cudaFuncAttributeMaxDynamicSharedMemorySize, GEMM_SMEM);
    cudaFuncSetAttribute(gemm_wo,  cudaFuncAttributeMaxDynamicSharedMemorySize, GEMM_SMEM);
    cudaFuncSetAttribute(attn_mma, cudaFuncAttributeMaxDynamicSharedMemorySize, ATT_SMEM);

    // convert activations (fp16 split) + weights (fp16 hi, transposed, packed)
    conv_act<<<SEQ * HID / 512, 256>>>(hidden);
    conv_wt<<<dim3(HID / 32, HID / 32), dim3(32, 8)>>>(Wq, Wqkvp, HID);
    conv_wt<<<dim3(KVW / 32, HID / 32), dim3(32, 8)>>>(Wk, Wqkvp + (size_t)HID * HID, KVW);
    conv_wt<<<dim3(KVW / 32, HID / 32), dim3(32, 8)>>>(Wv, Wqkvp + (size_t)(HID + KVW) * HID, KVW);
    conv_wt<<<dim3(HID / 32, HID / 32), dim3(32, 8)>>>(Wo, Wop, HID);

    // fused QKV projection (fp16 2-term)
    gemm_qkv<<<dim3(NQKV / 128, SEQ / 128), 256, GEMM_SMEM>>>();

    // per-head RMSNorm + RoPE + bf16 splits
    norm_rope_kernel<<<dim3(SEQ, NH + 2 * NKV), HD>>>(cosT, sinT, qs, ks);

    // causal GQA attention (bf16 3-term; writes fp16 AO splits)
    attn_mma<<<dim3(SEQ / 128, NH), 256, ATT_SMEM>>>();

    // output projection (fp16 2-term)
    gemm_wo<<<dim3(HID / 128, SEQ / 128), 256, GEMM_SMEM>>>();

    // final RMSNorm -> d_out
    final_norm_kernel<<<SEQ, 256>>>(ls, out);
}

// round 7
// speedup vs baseline: 4.7511x; 1.1498x over previous
#include <cuda_runtime.h>
#include <cuda_bf16.h>
#include <cuda_fp16.h>
#include <cstdint>
#include <math.h>

#define SEQ 2048
#define HID 2048
#define HD  128
#define NH  16
#define NKV 4
#define KVW (NKV*HD)           // 512
#define NQKV (HID + 2*KVW)     // 3072
#define EPSV 1e-6f
#define BKG 64
#define NSTG 4
#define KCH (HID / BKG)        // 32 k-chunks
#define GP  72                 // gemm smem row stride (halves)

// ---------------- scratch ----------------------------------------------------
__device__ float g_Q[SEQ * HID];
__device__ float g_K[SEQ * KVW];
__device__ float g_V[SEQ * KVW];
__device__ float g_Y[SEQ * HID];

__device__ __half g_Ah[SEQ * HID];               // hidden split hi
__device__ __half g_Al[SEQ * HID];               // hidden split lo
__device__ __half g_AOh[SEQ * HID];              // attention-out split hi
__device__ __half g_AOl[SEQ * HID];
__device__ __half g_Wqkv[NQKV * HID];            // W^T fp16
__device__ __half g_Wo[HID * HID];

__device__ __half g_Qh[SEQ * HID];               // Q split hi (post norm/rope)
__device__ __half g_Ql[SEQ * HID];               // Q split lo
__device__ __half g_Kf[SEQ * KVW];               // K fp16 (single)
__device__ __half g_Vf[SEQ * KVW];               // V fp16 (single)

// ======================= helpers =============================================
__device__ __forceinline__ uint32_t smem_u32(const void* p) {
    uint32_t a;
    asm("{ .reg .u64 t; cvta.to.shared.u64 t, %1; cvt.u32.u64 %0, t; }" : "=r"(a) : "l"(p));
    return a;
}
__device__ __forceinline__ void ldsm4(uint32_t* r, uint32_t addr) {
    asm volatile("ldmatrix.sync.aligned.m8n8.x4.shared.b16 {%0,%1,%2,%3}, [%4];"
        : "=r"(r[0]), "=r"(r[1]), "=r"(r[2]), "=r"(r[3]) : "r"(addr));
}
__device__ __forceinline__ void ldsm4t(uint32_t* r, uint32_t addr) {
    asm volatile("ldmatrix.sync.aligned.m8n8.x4.trans.shared.b16 {%0,%1,%2,%3}, [%4];"
        : "=r"(r[0]), "=r"(r[1]), "=r"(r[2]), "=r"(r[3]) : "r"(addr));
}
__device__ __forceinline__ void mma_f16(float* c, const uint32_t* a, const uint32_t* b) {
    asm volatile(
        "mma.sync.aligned.m16n8k16.row.col.f32.f16.f16.f32 "
        "{%0,%1,%2,%3}, {%4,%5,%6,%7}, {%8,%9}, {%0,%1,%2,%3};"
        : "+f"(c[0]), "+f"(c[1]), "+f"(c[2]), "+f"(c[3])
        : "r"(a[0]), "r"(a[1]), "r"(a[2]), "r"(a[3]), "r"(b[0]), "r"(b[1]));
}
__device__ __forceinline__ void cpa16(void* s, const void* g) {
    uint32_t sa = smem_u32(s);
    asm volatile("cp.async.cg.shared.global [%0], [%1], 16;" :: "r"(sa), "l"(g));
}

// ===== fp16 2-term GEMM core: C = (Ah+Al) @ B^T, 4-stage cp.async ===========
#define STAGE_HALF (3 * 128 * GP)
#define GEMM_SMEM  (NSTG * STAGE_HALF * 2)

struct GemmAcc { float a[4][4][4]; };

__device__ __forceinline__ void gemm_core(const __half* __restrict__ Ah,
                                          const __half* __restrict__ Al,
                                          const __half* __restrict__ B,
                                          int bm, int bn, __half* gs, GemmAcc& G)
{
    const int tid  = threadIdx.x;
    const int wid  = tid >> 5, lane = tid & 31;
    const int wm   = wid & 1, wn = wid >> 1;
    const uint32_t sbase = smem_u32(gs);

#define ISSUE(c) do {                                                                   \
    int _k0 = (c) * BKG;                                                                \
    __half* _sA = gs + ((c) % NSTG) * STAGE_HALF;                                       \
    __half* _sL = _sA + 128 * GP;                                                       \
    __half* _sB = _sL + 128 * GP;                                                       \
    _Pragma("unroll")                                                                   \
    for (int _i = 0; _i < 4; _i++) {                                                    \
        int _id = _i * 256 + tid; int _r = _id >> 3, _u = _id & 7;                      \
        int _so = _r * GP + _u * 8;                                                     \
        size_t _ga = (size_t)(bm + _r) * HID + _k0 + _u * 8;                            \
        cpa16(_sA + _so, Ah + _ga);                                                     \
        cpa16(_sL + _so, Al + _ga);                                                     \
        cpa16(_sB + _so, B + (size_t)(bn + _r) * HID + _k0 + _u * 8);                   \
    }                                                                                   \
    asm volatile("cp.async.commit_group;" ::: "memory");                                \
} while (0)

#pragma unroll
    for (int i = 0; i < 4; i++)
#pragma unroll
        for (int j = 0; j < 4; j++)
#pragma unroll
            for (int k = 0; k < 4; k++) G.a[i][j][k] = 0.0f;

    ISSUE(0); ISSUE(1); ISSUE(2);

    const uint32_t aOff = (uint32_t)((wm * 64 + (lane & 15)) * GP + ((lane >> 4) << 3)) * 2;
    const uint32_t bOff = (uint32_t)((wn * 32 + (lane & 7) + (((lane >> 4) & 1) << 3)) * GP
                                     + (((lane >> 3) & 1) << 3)) * 2;

    for (int c = 0; c < KCH; c++) {
        asm volatile("cp.async.wait_group 2;" ::: "memory");
        __syncthreads();
        if (c + 3 < KCH) { ISSUE(c + 3); }
        else { asm volatile("cp.async.commit_group;" ::: "memory"); }

        const uint32_t aB = sbase + (c % NSTG) * (STAGE_HALF * 2);
        const uint32_t lB = aB + 128 * GP * 2;
        const uint32_t bB = lB + 128 * GP * 2;
#pragma unroll
        for (int ks = 0; ks < 4; ks++) {
            uint32_t ah[4][4], al[4][4], bfr[2][4];
#pragma unroll
            for (int mi = 0; mi < 4; mi++) {
                ldsm4(ah[mi], aB + aOff + mi * (16 * GP * 2) + ks * 32);
                ldsm4(al[mi], lB + aOff + mi * (16 * GP * 2) + ks * 32);
            }
#pragma unroll
            for (int nj = 0; nj < 2; nj++)
                ldsm4(bfr[nj], bB + bOff + nj * (16 * GP * 2) + ks * 32);
#pragma unroll
            for (int mi = 0; mi < 4; mi++)
#pragma unroll
                for (int ni = 0; ni < 4; ni++) {
                    mma_f16(G.a[mi][ni], ah[mi], &bfr[ni >> 1][(ni & 1) * 2]);
                    mma_f16(G.a[mi][ni], al[mi], &bfr[ni >> 1][(ni & 1) * 2]);
                }
        }
    }
#undef ISSUE
}

// ---- fused QKV projection ----
__global__ __launch_bounds__(256) void gemm_qkv()
{
    extern __shared__ char dynsm[];
    GemmAcc G;
    const int bm = blockIdx.y * 128, bn = blockIdx.x * 128;
    gemm_core(g_Ah, g_Al, g_Wqkv, bm, bn, (__half*)dynsm, G);

    float* Cb; int Nw, c0;
    if (bn < HID)            { Cb = g_Q; Nw = HID; c0 = bn; }
    else if (bn < HID + KVW) { Cb = g_K; Nw = KVW; c0 = bn - HID; }
    else                     { Cb = g_V; Nw = KVW; c0 = bn - HID - KVW; }

    const int lane = threadIdx.x & 31, wid = threadIdx.x >> 5;
    const int cr = bm + (wid & 1) * 64 + (lane >> 2);
    const int cc = c0 + (wid >> 1) * 32 + (lane & 3) * 2;
#pragma unroll
    for (int mi = 0; mi < 4; mi++)
#pragma unroll
        for (int ni = 0; ni < 4; ni++) {
            *(float2*)&Cb[(size_t)(cr + mi * 16) * Nw + cc + ni * 8] =
                make_float2(G.a[mi][ni][0], G.a[mi][ni][1]);
            *(float2*)&Cb[(size_t)(cr + mi * 16 + 8) * Nw + cc + ni * 8] =
                make_float2(G.a[mi][ni][2], G.a[mi][ni][3]);
        }
}

// ---- Wo projection ----
__global__ __launch_bounds__(256) void gemm_wo()
{
    extern __shared__ char dynsm[];
    GemmAcc G;
    const int bm = blockIdx.y * 128, bn = blockIdx.x * 128;
    gemm_core(g_AOh, g_AOl, g_Wo, bm, bn, (__half*)dynsm, G);

    const int lane = threadIdx.x & 31, wid = threadIdx.x >> 5;
    const int cr = bm + (wid & 1) * 64 + (lane >> 2);
    const int cc = bn + (wid >> 1) * 32 + (lane & 3) * 2;
#pragma unroll
    for (int mi = 0; mi < 4; mi++)
#pragma unroll
        for (int ni = 0; ni < 4; ni++) {
            *(float2*)&g_Y[(size_t)(cr + mi * 16) * HID + cc + ni * 8] =
                make_float2(G.a[mi][ni][0], G.a[mi][ni][1]);
            *(float2*)&g_Y[(size_t)(cr + mi * 16 + 8) * HID + cc + ni * 8] =
                make_float2(G.a[mi][ni][2], G.a[mi][ni][3]);
        }
}

// =========== split-convert hidden: f32 -> Ah, Al fp16 ========================
__global__ void conv_act(const float* __restrict__ X)
{
    int idx = (blockIdx.x * blockDim.x + threadIdx.x) * 2;
    float2 x = *(const float2*)(X + idx);
    __half h0 = __float2half_rn(x.x);
    __half h1 = __float2half_rn(x.y);
    __half l0 = __float2half_rn(x.x - __half2float(h0));
    __half l1 = __float2half_rn(x.y - __half2float(h1));
    __half2 hv; hv.x = h0; hv.y = h1;
    __half2 lv; lv.x = l0; lv.y = l1;
    *(__half2*)(g_Ah + idx) = hv;
    *(__half2*)(g_Al + idx) = lv;
}

// ==== transpose: W[HID,N] f32 -> Wt[N,HID] fp16 ==============================
__global__ void conv_wt(const float* __restrict__ W, __half* __restrict__ Wt, int N)
{
    __shared__ float t[32][33];
    int n0 = blockIdx.x * 32, k0 = blockIdx.y * 32;
    int tx = threadIdx.x, ty0 = threadIdx.y;
#pragma unroll
    for (int i = 0; i < 4; i++) {
        int ty = ty0 + i * 8;
        t[ty][tx] = W[(size_t)(k0 + ty) * N + n0 + tx];
    }
    __syncthreads();
#pragma unroll
    for (int i = 0; i < 4; i++) {
        int n = n0 + ty0 + i * 8;
        int k = k0 + tx;
        Wt[(size_t)n * HID + k] = __float2half_rn(t[tx][ty0 + i * 8]);
    }
}

// -------- per-head RMSNorm+RoPE -> Q fp16 split, K fp16; V fp16 --------------
__global__ void norm_rope_kernel(const float* __restrict__ cosT,
                                 const float* __restrict__ sinT,
                                 const float* __restrict__ qscale,
                                 const float* __restrict__ kscale)
{
    int s = blockIdx.x;
    int h = blockIdx.y;   // 0..15 Q, 16..19 K, 20..23 V
    int d = threadIdx.x;

    if (h >= NH + NKV) {
        size_t i = (size_t)s * KVW + (h - NH - NKV) * HD + d;
        g_Vf[i] = __float2half_rn(g_V[i]);
        return;
    }

    const float* base;
    const float* sc;
    size_t oidx;
    if (h < NH) { base = g_Q + (size_t)s * HID + h * HD; sc = qscale;
                  oidx = (size_t)s * HID + h * HD + d; }
    else        { base = g_K + (size_t)s * KVW + (h - NH) * HD; sc = kscale;
                  oidx = (size_t)s * KVW + (h - NH) * HD + d; }

    float x = base[d];
    float v = x * x;
#pragma unroll
    for (int m = 16; m > 0; m >>= 1) v += __shfl_xor_sync(0xffffffffu, v, m);

    __shared__ float ws[4];
    __shared__ float rn[HD];
    if ((d & 31) == 0) ws[d >> 5] = v;
    __syncthreads();
    float tot = ws[0] + ws[1] + ws[2] + ws[3];
    float inv = rsqrtf(tot * (1.0f / HD) + EPSV);

    float r = x * inv * sc[d];
    rn[d] = r;
    __syncthreads();
    float rot = (d < 64) ? -rn[d + 64] : rn[d - 64];
    float c  = cosT[(size_t)s * HD + d];
    float sn = sinT[(size_t)s * HD + d];
    float out = r * c + rot * sn;

    if (h < NH) {
        __half hi = __float2half_rn(out);
        g_Qh[oidx] = hi;
        g_Ql[oidx] = __float2half_rn(out - __half2float(hi));
    } else {
        g_Kf[oidx] = __float2half_rn(out);
    }
}

// ---------------- causal GQA flash attention, fp16 2-term HMMA ---------------
// 256 threads = 8 warps; 128 q-rows per CTA; K/V 64-row tiles double-buffered.
#define AP 136
#define KVBUF (2 * 64 * AP)
#define ATT_SMEM ((2 * 128 * AP + 2 * KVBUF) * 2)

__global__ __launch_bounds__(256) void attn_mma()
{
    extern __shared__ char dynsm[];
    __half* sm = (__half*)dynsm;
    __half* Qh = sm;
    __half* Ql = sm + 128 * AP;
    __half* KV = sm + 2 * 128 * AP;

    const int qb = 15 - blockIdx.x;
    const int h  = blockIdx.y;
    const int kv = h >> 2;
    const int tid = threadIdx.x, w = tid >> 5, l = tid & 31;
    const float scl = 0.08838834764831845f;
    const int kmax = 2 * qb + 1;

    const __half* gkf = g_Kf + kv * HD;
    const __half* gvf = g_Vf + kv * HD;

#define ISSUE_KV(kb) do {                                                              \
    __half* _d = KV + ((kb) & 1) * KVBUF;                                              \
    size_t _g0 = (size_t)((kb) * 64) * KVW;                                            \
    _Pragma("unroll")                                                                  \
    for (int _i = 0; _i < 4; _i++) {                                                   \
        int _id = _i * 256 + tid; int _r = _id >> 4, _u = _id & 15;                    \
        size_t _go = _g0 + (size_t)_r * KVW + _u * 8;                                  \
        int _so = _r * AP + _u * 8;                                                    \
        cpa16(_d + _so,           gkf + _go);                                          \
        cpa16(_d + 64 * AP + _so, gvf + _go);                                          \
    }                                                                                  \
    asm volatile("cp.async.commit_group;" ::: "memory");                               \
} while (0)

    ISSUE_KV(0);

    {
        const __half* gh = g_Qh + (size_t)(qb * 128) * HID + h * HD;
        const __half* gl = g_Ql + (size_t)(qb * 128) * HID + h * HD;
#pragma unroll
        for (int i = 0; i < 8; i++) {
            int id = i * 256 + tid;
            int r = id >> 4, u = id & 15;
            *(uint4*)(Qh + r * AP + u * 8) = *(const uint4*)(gh + (size_t)r * HID + u * 8);
            *(uint4*)(Ql + r * AP + u * 8) = *(const uint4*)(gl + (size_t)r * HID + u * 8);
        }
    }

    const uint32_t qa  = smem_u32(Qh), qla = smem_u32(Ql);
    const uint32_t aOff = (uint32_t)((w * 16 + (l & 15)) * AP + ((l >> 4) << 3)) * 2;

    float m0 = -1e30f, m1 = -1e30f, ls0 = 0.0f, ls1 = 0.0f;
    float accO[16][4];
#pragma unroll
    for (int i = 0; i < 16; i++)
#pragma unroll
        for (int j = 0; j < 4; j++) accO[i][j] = 0.0f;

    for (int kb = 0; kb <= kmax; kb++) {
        asm volatile("cp.async.wait_group 0;" ::: "memory");
        __syncthreads();
        if (kb < kmax) ISSUE_KV(kb + 1);

        const __half* buf = KV + (kb & 1) * KVBUF;
        const uint32_t ka = smem_u32(buf);
        const uint32_t va = ka + 64 * AP * 2;

        // ---- S = (Qh + Ql) · K ----
        float S[8][4];
#pragma unroll
        for (int t = 0; t < 8; t++)
#pragma unroll
            for (int e = 0; e < 4; e++) S[t][e] = 0.0f;

#pragma unroll
        for (int ks = 0; ks < 8; ks++) {
            uint32_t afh[4], afl[4], bf2[4][4];
            ldsm4(afh, qa  + aOff + ks * 32);
            ldsm4(afl, qla + aOff + ks * 32);
#pragma unroll
            for (int g = 0; g < 4; g++)
                ldsm4(bf2[g], ka + (uint32_t)((g * 16 + (l & 7) + (((l >> 4) & 1) << 3)) * AP
                                              + (((l >> 3) & 1) << 3)) * 2 + ks * 32);
#pragma unroll
            for (int t = 0; t < 8; t++)
                mma_f16(S[t], afh, &bf2[t >> 1][(t & 1) * 2]);
#pragma unroll
            for (int t = 0; t < 8; t++)
                mma_f16(S[t], afl, &bf2[t >> 1][(t & 1) * 2]);
        }

#pragma unroll
        for (int t = 0; t < 8; t++)
#pragma unroll
            for (int e = 0; e < 4; e++) S[t][e] *= scl;

        if (kb >= 2 * qb) {
            int r0 = qb * 128 + w * 16 + (l >> 2), r1 = r0 + 8;
            int cbase = kb * 64 + (l & 3) * 2;
#pragma unroll
            for (int t = 0; t < 8; t++) {
                int cb = cbase + t * 8;
                if (cb     > r0) S[t][0] = -1e30f;
                if (cb + 1 > r0) S[t][1] = -1e30f;
                if (cb     > r1) S[t][2] = -1e30f;
                if (cb + 1 > r1) S[t][3] = -1e30f;
            }
        }

        float mx0 = -1e30f, mx1 = -1e30f;
#pragma unroll
        for (int t = 0; t < 8; t++) {
            mx0 = fmaxf(mx0, fmaxf(S[t][0], S[t][1]));
            mx1 = fmaxf(mx1, fmaxf(S[t][2], S[t][3]));
        }
        mx0 = fmaxf(mx0, __shfl_xor_sync(0xffffffffu, mx0, 1));
        mx0 = fmaxf(mx0, __shfl_xor_sync(0xffffffffu, mx0, 2));
        mx1 = fmaxf(mx1, __shfl_xor_sync(0xffffffffu, mx1, 1));
        mx1 = fmaxf(mx1, __shfl_xor_sync(0xffffffffu, mx1, 2));

        float nm0 = fmaxf(m0, mx0), nm1 = fmaxf(m1, mx1);
        float cr0 = __expf(m0 - nm0), cr1 = __expf(m1 - nm1);
        m0 = nm0; m1 = nm1;
        ls0 *= cr0; ls1 *= cr1;
#pragma unroll
        for (int t = 0; t < 16; t++) {
            accO[t][0] *= cr0; accO[t][1] *= cr0;
            accO[t][2] *= cr1; accO[t][3] *= cr1;
        }

        // P = exp(S - m), split into fp16 Ph + Pl register fragments
        uint32_t Pha[4][4], Pla[4][4];
        float rs0 = 0.0f, rs1 = 0.0f;
#pragma unroll
        for (int t = 0; t < 8; t++) {
            float p0 = __expf(S[t][0] - nm0), p1 = __expf(S[t][1] - nm0);
            float p2 = __expf(S[t][2] - nm1), p3 = __expf(S[t][3] - nm1);
            rs0 += p0 + p1; rs1 += p2 + p3;
            __half2 h01 = __floats2half2_rn(p0, p1);
            __half2 h23 = __floats2half2_rn(p2, p3);
            __half2 l01 = __floats2half2_rn(p0 - __half2float(h01.x), p1 - __half2float(h01.y));
            __half2 l23 = __floats2half2_rn(p2 - __half2float(h23.x), p3 - __half2float(h23.y));
            int kc = t >> 1, hi = (t & 1) * 2;
            Pha[kc][hi]     = *(uint32_t*)&h01;
            Pha[kc][hi + 1] = *(uint32_t*)&h23;
            Pla[kc][hi]     = *(uint32_t*)&l01;
            Pla[kc][hi + 1] = *(uint32_t*)&l23;
        }
        rs0 += __shfl_xor_sync(0xffffffffu, rs0, 1);
        rs0 += __shfl_xor_sync(0xffffffffu, rs0, 2);
        rs1 += __shfl_xor_sync(0xffffffffu, rs1, 1);
        rs1 += __shfl_xor_sync(0xffffffffu, rs1, 2);
        ls0 += rs0; ls1 += rs1;

        // ---- PV: acc += (Ph + Pl) · V ----
#pragma unroll
        for (int kc = 0; kc < 4; kc++) {
            uint32_t vb[8][4];
#pragma unroll
            for (int g = 0; g < 8; g++)
                ldsm4t(vb[g], va + (uint32_t)((kc * 16 + (l & 15)) * AP
                                              + (g * 16 + ((l >> 4) << 3))) * 2);
#pragma unroll
            for (int nd = 0; nd < 16; nd++)
                mma_f16(accO[nd], Pha[kc], &vb[nd >> 1][(nd & 1) * 2]);
#pragma unroll
            for (int nd = 0; nd < 16; nd++)
                mma_f16(accO[nd], Pla[kc], &vb[nd >> 1][(nd & 1) * 2]);
        }
    }
#undef ISSUE_KV

    // epilogue: write AOh / AOl fp16 splits
    float inv0 = 1.0f / ls0, inv1 = 1.0f / ls1;
    int r0 = qb * 128 + w * 16 + (l >> 2);
    int cc = h * HD + (l & 3) * 2;
#pragma unroll
    for (int nd = 0; nd < 16; nd++) {
        float v00 = accO[nd][0] * inv0, v01 = accO[nd][1] * inv0;
        float v10 = accO[nd][2] * inv1, v11 = accO[nd][3] * inv1;
        __half2 h0 = __floats2half2_rn(v00, v01);
        __half2 l0v = __floats2half2_rn(v00 - __half2float(h0.x), v01 - __half2float(h0.y));
        __half2 h1 = __floats2half2_rn(v10, v11);
        __half2 l1v = __floats2half2_rn(v10 - __half2float(h1.x), v11 - __half2float(h1.y));
        size_t b0 = (size_t)r0 * HID + cc + nd * 8;
        size_t b1 = (size_t)(r0 + 8) * HID + cc + nd * 8;
        *(__half2*)(g_AOh + b0) = h0;
        *(__half2*)(g_AOl + b0) = l0v;
        *(__half2*)(g_AOh + b1) = h1;
        *(__half2*)(g_AOl + b1) = l1v;
    }
}

// ---------------- final RMSNorm ----------------------------------------------
__global__ void final_norm_kernel(const float* __restrict__ sc, float* __restrict__ out)
{
    int s = blockIdx.x;
    const float* y = g_Y + (size_t)s * HID;
    float v = 0.0f;
    for (int d = threadIdx.x; d < HID; d += 256) { float x = y[d]; v += x * x; }
#pragma unroll
    for (int m = 16; m > 0; m >>= 1) v += __shfl_xor_sync(0xffffffffu, v, m);
    __shared__ float ws[8];
    if ((threadIdx.x & 31) == 0) ws[threadIdx.x >> 5] = v;
    __syncthreads();
    float tot = 0.0f;
#pragma unroll
    for (int i = 0; i < 8; i++) tot += ws[i];
    float inv = rsqrtf(tot * (1.0f / HID) + EPSV);
    for (int d = threadIdx.x; d < HID; d += 256)
        out[(size_t)s * HID + d] = y[d] * inv * sc[d];
}

// ---------------- launch -----------------------------------------------------
extern "C" void kernel_launch(void* const* d_in, const int* in_sizes, int n_in,
                              void* d_out, int out_size)
{
    const float* hidden = (const float*)d_in[0];
    const float* cosT   = (const float*)d_in[1];
    const float* sinT   = (const float*)d_in[2];
    const float* Wq     = (const float*)d_in[3];
    const float* Wk     = (const float*)d_in[4];
    const float* Wv     = (const float*)d_in[5];
    const float* Wo     = (const float*)d_in[6];
    const float* qs     = (const float*)d_in[7];
    const float* ks     = (const float*)d_in[8];
    const float* ls     = (const float*)d_in[9];
    float* out = (float*)d_out;

    __half *Wqkvp, *Wop;
    cudaGetSymbolAddress((void**)&Wqkvp, g_Wqkv);
    cudaGetSymbolAddress((void**)&Wop,   g_Wo);

    cudaFuncSetAttribute(gemm_qkv, cudaFuncAttributeMaxDynamicSharedMemorySize, GEMM_SMEM);
    cudaFuncSetAttribute(gemm_wo,  cudaFuncAttributeMaxDynamicSharedMemorySize, GEMM_SMEM);
    cudaFuncSetAttribute(attn_mma, cudaFuncAttributeMaxDynamicSharedMemorySize, ATT_SMEM);

    // convert activations (fp16 split) + weights (fp16, transposed, packed)
    conv_act<<<SEQ * HID / 512, 256>>>(hidden);
    conv_wt<<<dim3(HID / 32, HID / 32), dim3(32, 8)>>>(Wq, Wqkvp, HID);
    conv_wt<<<dim3(KVW / 32, HID / 32), dim3(32, 8)>>>(Wk, Wqkvp + (size_t)HID * HID, KVW);
    conv_wt<<<dim3(KVW / 32, HID / 32), dim3(32, 8)>>>(Wv, Wqkvp + (size_t)(HID + KVW) * HID, KVW);
    conv_wt<<<dim3(HID / 32, HID / 32), dim3(32, 8)>>>(Wo, Wop, HID);

    // fused QKV projection (fp16 2-term)
    gemm_qkv<<<dim3(NQKV / 128, SEQ / 128), 256, GEMM_SMEM>>>();

    // per-head RMSNorm + RoPE + fp16 outputs
    norm_rope_kernel<<<dim3(SEQ, NH + 2 * NKV), HD>>>(cosT, sinT, qs, ks);

    // causal GQA attention (fp16 2-term QK and PV)
    attn_mma<<<dim3(SEQ / 128, NH), 256, ATT_SMEM>>>();

    // output projection (fp16 2-term)
    gemm_wo<<<dim3(HID / 128, SEQ / 128), 256, GEMM_SMEM>>>();

    // final RMSNorm -> d_out
    final_norm_kernel<<<SEQ, 256>>>(ls, out);
}